// round 10
// baseline (speedup 1.0000x reference)
#include <cuda_runtime.h>
#include <cuda_bf16.h>
#include <cstdint>

#define NN 200000
#define UU 20000
#define HH 256

#define BM 64
#define BN 64
#define BK 32                  // k-bytes per tile (int8)
#define STG 8192               // stage bytes: A hi/lo 2K+2K, B hi/lo 2K+2K
#define NSTG 3
#define ASCL 4096.0f           // A fixed-point scale 2^12
#define BSCL 32768.0f          // B fixed-point scale 2^15
#define INVS 7.450580596923828e-9f   // 2^-27

// ---------------- scratch (device globals) -------------------------------------
__device__ __align__(16) signed char g_Ah8[(size_t)NN * HH];
__device__ __align__(16) signed char g_Al8[(size_t)NN * HH];
__device__ __align__(16) signed char g_Wh8[(size_t)UU * HH];   // normalized ws digits
__device__ __align__(16) signed char g_Wl8[(size_t)UU * HH];
__device__ __align__(16) signed char g_Mh8 [HH * HH], g_Ml8 [HH * HH];  // M^T digits (n-major)
__device__ __align__(16) signed char g_C1h8[HH * HH], g_C1l8[HH * HH];  // C1^T digits
__device__ __align__(16) signed char g_Bth8[HH * HH], g_Btl8[HH * HH];  // W1[:,H:] digits (n-major)
__device__ __align__(16) float g_D  [UU * HH];
__device__ __align__(16) float g_sim[NN];
__device__ int g_list[NN];          // CSR row lists
__device__ int g_off [UU + 1];
__device__ int g_cnt [UU];
__device__ int g_cnt2[UU];

// ---------------- helpers -------------------------------------------------------
__device__ __forceinline__ void ldsm4(uint32_t* r, uint32_t addr) {
    asm volatile("ldmatrix.sync.aligned.m8n8.x4.shared.b16 {%0,%1,%2,%3}, [%4];"
                 : "=r"(r[0]), "=r"(r[1]), "=r"(r[2]), "=r"(r[3]) : "r"(addr));
}
__device__ __forceinline__ void mma_s8(int* c, const uint32_t* a, const uint32_t* b) {
    asm volatile("mma.sync.aligned.m16n8k32.row.col.s32.s8.s8.s32 "
                 "{%0,%1,%2,%3}, {%4,%5,%6,%7}, {%8,%9}, {%0,%1,%2,%3};"
                 : "+r"(c[0]), "+r"(c[1]), "+r"(c[2]), "+r"(c[3])
                 : "r"(a[0]), "r"(a[1]), "r"(a[2]), "r"(a[3]), "r"(b[0]), "r"(b[1]));
}
__device__ __forceinline__ void cpa16(uint32_t dst, const void* src, bool v) {
    int sz = v ? 16 : 0;
    asm volatile("cp.async.cg.shared.global [%0], [%1], 16, %2;"
                 :: "r"(dst), "l"(src), "r"(sz));
}
// swizzled byte offset of (row, 16B-chunk ch) in a 32B-stride tile
__device__ __forceinline__ uint32_t swz8(int row, int ch) {
    return (uint32_t)(row * 32 + ((ch ^ ((row >> 2) & 1)) * 16));
}
// int16 -> 2 signed int8 digits
__device__ __forceinline__ void qsplit(float x, float scl, int& hi, int& lo) {
    int v = __float2int_rn(x * scl);
    hi = (v + 128) >> 8;
    lo = v - (hi << 8);
}
__device__ __forceinline__ float comb(int hh, int md, int ll) {
    return fmaf((float)hh, 65536.0f, fmaf((float)md, 256.0f, (float)ll)) * INVS;
}

// ---------------- init scratch -------------------------------------------------
__global__ void k_zero() {
    int idx = blockIdx.x * 256 + threadIdx.x;
    if (idx < NN) g_sim[idx] = 0.0f;
    if (idx < UU) { g_cnt[idx] = 0; g_cnt2[idx] = 0; }
}

// ---------------- CSR build: hist -> scan -> fill --------------------------------
__global__ void k_hist(const int* __restrict__ ids, int n) {
    int i = blockIdx.x * 256 + threadIdx.x;
    if (i < n) atomicAdd(&g_cnt[ids[i]], 1);
}
__global__ void k_scan() {             // single block, 256 threads
    __shared__ int ps[256];
    const int C = (UU + 255) / 256;
    int t = threadIdx.x;
    int s = 0;
    for (int j = 0; j < C; j++) { int i = t * C + j; if (i < UU) s += g_cnt[i]; }
    ps[t] = s;
    __syncthreads();
    int acc = 0;
    for (int j = 0; j < t; j++) acc += ps[j];
    int run = acc;
    for (int j = 0; j < C; j++) {
        int i = t * C + j;
        if (i < UU) { g_off[i] = run; run += g_cnt[i]; }
    }
    if (t == 255) g_off[UU] = run;
}
__global__ void k_fill(const int* __restrict__ ids, int n) {
    int i = blockIdx.x * 256 + threadIdx.x;
    if (i < n) {
        int uid = ids[i];
        int pos = g_off[uid] + atomicAdd(&g_cnt2[uid], 1);
        g_list[pos] = i;
    }
}

// ---------------- coalesced precompute GEMMs -----------------------------------
// z==0: M[a,t]  = Wq[a,:]·Wk[t,:]      -> g_Mh8/l8 [t*256+a]
// z==1: C1[a,t] = Wv[a,:]·W1[t,0:256]  -> g_C1h8/l8[t*256+a]
__global__ void k_prepT(const float* __restrict__ Wq, const float* __restrict__ Wk,
                        const float* __restrict__ Wv, const float* __restrict__ W1) {
    __shared__ float As[32 * 129];
    __shared__ float Bs[32 * 129];
    int z = blockIdx.z;
    int tid = threadIdx.x;
    int abase = blockIdx.y * 32;
    int tbase = blockIdx.x * 32;
    const float* Ag = z ? Wv : Wq;
    int tx = tid & 31, ty = tid >> 5;
    float acc[4] = {0.f, 0.f, 0.f, 0.f};

    for (int kt = 0; kt < 256; kt += 128) {
        #pragma unroll
        for (int i = 0; i < 16; i++) {
            int f = tid + i * 256;
            int r = f >> 7, c = f & 127;
            As[r * 129 + c] = Ag[(abase + r) * 256 + kt + c];
            Bs[r * 129 + c] = z ? W1[(tbase + r) * 512 + kt + c]
                                : Wk[(tbase + r) * 256 + kt + c];
        }
        __syncthreads();
        #pragma unroll 4
        for (int k = 0; k < 128; k++) {
            float av = As[tx * 129 + k];
            #pragma unroll
            for (int j = 0; j < 4; j++) acc[j] += av * Bs[(ty + 8 * j) * 129 + k];
        }
        __syncthreads();
    }
    int a = abase + tx;
    #pragma unroll
    for (int j = 0; j < 4; j++) {
        int t = tbase + ty + 8 * j;
        int hi, lo;
        qsplit(acc[j], BSCL, hi, lo);
        if (z == 0) { g_Mh8 [t * 256 + a] = (signed char)hi; g_Ml8 [t * 256 + a] = (signed char)lo; }
        else        { g_C1h8[t * 256 + a] = (signed char)hi; g_C1l8[t * 256 + a] = (signed char)lo; }
    }
}

// Bt digits (n-major): W1[j*512+256+k]
__global__ void k_prepBt(const float* __restrict__ W1) {
    int j = blockIdx.x, k = threadIdx.x;
    int hi, lo;
    qsplit(W1[j * 512 + 256 + k], BSCL, hi, lo);
    g_Bth8[j * 256 + k] = (signed char)hi;
    g_Btl8[j * 256 + k] = (signed char)lo;
}

// ---------------- ue fp32 -> int8 digit planes ------------------------------------
__global__ void k_cvt8(const float4* __restrict__ src) {
    size_t i = (size_t)blockIdx.x * 256 + threadIdx.x;   // NN*HH/4 threads
    float4 v = src[i];
    int h0, l0, h1, l1, h2, l2, h3, l3;
    qsplit(v.x, ASCL, h0, l0);
    qsplit(v.y, ASCL, h1, l1);
    qsplit(v.z, ASCL, h2, l2);
    qsplit(v.w, ASCL, h3, l3);
    ((char4*)g_Ah8)[i] = make_char4((char)h0, (char)h1, (char)h2, (char)h3);
    ((char4*)g_Al8)[i] = make_char4((char)l0, (char)l1, (char)l2, (char)l3);
}

// ---------------- softmax gather: per-uid max/exp/normalized weighted sum --------
__global__ void k_gather(const float* __restrict__ ue) {
    int u    = blockIdx.x * 4 + (threadIdx.x >> 6);
    int lane = threadIdx.x & 63;
    if (u >= UU) return;
    int s = g_off[u], e = g_off[u + 1];

    float mx = -1e30f;
    for (int r = s; r < e; r++) mx = fmaxf(mx, g_sim[g_list[r]]);

    float den = 0.0f;
    float4 acc = make_float4(0.f, 0.f, 0.f, 0.f);
    for (int r = s; r < e; r++) {
        int row = g_list[r];
        float ev = expf(g_sim[row] - mx);
        den += ev;
        float4 v = *(const float4*)&ue[(size_t)row * 256 + lane * 4];
        acc.x += ev * v.x; acc.y += ev * v.y; acc.z += ev * v.z; acc.w += ev * v.w;
    }
    float inv = (e > s) ? (1.0f / den) : 0.0f;
    int h0, l0, h1, l1, h2, l2, h3, l3;
    qsplit(acc.x * inv, ASCL, h0, l0);
    qsplit(acc.y * inv, ASCL, h1, l1);
    qsplit(acc.z * inv, ASCL, h2, l2);
    qsplit(acc.w * inv, ASCL, h3, l3);
    size_t o = ((size_t)u * 256 + lane * 4) >> 2;
    ((char4*)g_Wh8)[o] = make_char4((char)h0, (char)h1, (char)h2, (char)h3);
    ((char4*)g_Wl8)[o] = make_char4((char)l0, (char)l1, (char)l2, (char)l3);
}

// ---------------- int8 tensor-core GEMM (BM=64 BN=64, 4 warps, 3 CTA/SM) ---------
// grid = (4, rowBlocks): blockIdx.x = 64-col quarter (co-resident quarters share A in L2)
// MODE 0: g_sim[row] += partial rowsum((A @ M) .* sess)               (A = ue)
// MODE 1: g_D = wsn @ Bt + b1                                          (A = wsn, extra = b1)
// MODE 2: out = relu(A @ C1 + g_D[ids])                                (A = ue)
template<int MODE>
__global__ __launch_bounds__(128, 3)
void k_mma8(const float* __restrict__ extra, const int* __restrict__ ids,
            float* __restrict__ outp, int nrows) {
    extern __shared__ __align__(16) char smem[];
    uint32_t sbase = (uint32_t)__cvta_generic_to_shared(smem);
    const int tid  = threadIdx.x;
    const int lane = tid & 31;
    const int wid  = tid >> 5;                 // 0..3
    const int mw = wid >> 1, nw = wid & 1;     // 2 x 2 warp grid, warp tile 32x32
    const int blockRow = blockIdx.y * BM;
    const int colBase  = blockIdx.x * BN;

    const signed char* Ahp = (MODE == 1) ? g_Wh8 : g_Ah8;
    const signed char* Alp = (MODE == 1) ? g_Wl8 : g_Al8;
    const signed char* Bhp = (MODE == 0) ? g_Mh8 : ((MODE == 1) ? g_Bth8 : g_C1h8);
    const signed char* Blp = (MODE == 0) ? g_Ml8 : ((MODE == 1) ? g_Btl8 : g_C1l8);

    int hh[2][4][4] = {}, md[2][4][4] = {}, ll[2][4][4] = {};

    // ---- loader: 4 cpa16 per thread per stage ----
    auto load_stage = [&](int kt, int s) {
        uint32_t db = sbase + (uint32_t)s * STG;
        int r = tid >> 1, ch = tid & 1;
        uint32_t dst = swz8(r, ch);
        int grow = blockRow + r;
        bool v = grow < nrows;
        size_t ga = (size_t)(v ? grow : 0) * HH + kt * BK + ch * 16;
        cpa16(db + 0    + dst, Ahp + ga, v);
        cpa16(db + 2048 + dst, Alp + ga, v);
        size_t gb = (size_t)(colBase + r) * HH + kt * BK + ch * 16;
        cpa16(db + 4096 + dst, Bhp + gb, true);
        cpa16(db + 6144 + dst, Blp + gb, true);
        asm volatile("cp.async.commit_group;" ::: "memory");
    };

    load_stage(0, 0);
    load_stage(1, 1);

    const int NKT = HH / BK;   // 8
    for (int kt = 0; kt < NKT; kt++) {
        if (kt < NKT - 1) asm volatile("cp.async.wait_group 1;" ::: "memory");
        else              asm volatile("cp.async.wait_group 0;" ::: "memory");
        __syncthreads();
        if (kt + 2 < NKT) load_stage(kt + 2, (kt + 2) % NSTG);

        uint32_t sb = sbase + (uint32_t)(kt % NSTG) * STG;
        uint32_t ahi[2][4], alo[2][4];
        #pragma unroll
        for (int t = 0; t < 2; t++) {
            int arow = mw * 32 + t * 16 + (lane & 15);
            uint32_t ao = swz8(arow, lane >> 4);
            ldsm4(ahi[t], sb + 0    + ao);
            ldsm4(alo[t], sb + 2048 + ao);
        }
        #pragma unroll
        for (int p = 0; p < 2; p++) {
            int brow = nw * 32 + p * 16 + (lane & 7) + ((lane >> 4) << 3);
            uint32_t bo = swz8(brow, (lane >> 3) & 1);
            uint32_t bh[4], bl[4];
            ldsm4(bh, sb + 4096 + bo);
            ldsm4(bl, sb + 6144 + bo);
            // sweeps: hh, mid(a_h*b_l), mid(a_l*b_h), ll — reuse distance 4
            #pragma unroll
            for (int t = 0; t < 2; t++)
                #pragma unroll
                for (int q = 0; q < 2; q++)
                    mma_s8(hh[t][p * 2 + q], ahi[t], &bh[2 * q]);
            #pragma unroll
            for (int t = 0; t < 2; t++)
                #pragma unroll
                for (int q = 0; q < 2; q++)
                    mma_s8(md[t][p * 2 + q], ahi[t], &bl[2 * q]);
            #pragma unroll
            for (int t = 0; t < 2; t++)
                #pragma unroll
                for (int q = 0; q < 2; q++)
                    mma_s8(md[t][p * 2 + q], alo[t], &bh[2 * q]);
            #pragma unroll
            for (int t = 0; t < 2; t++)
                #pragma unroll
                for (int q = 0; q < 2; q++)
                    mma_s8(ll[t][p * 2 + q], alo[t], &bl[2 * q]);
        }
    }

    const int lr = lane >> 2;           // 0..7
    const int lc = (lane & 3) * 2;      // 0,2,4,6

    if (MODE == 0) {
        float part[2][2] = {{0.f, 0.f}, {0.f, 0.f}};
        #pragma unroll
        for (int t = 0; t < 2; t++) {
            int row0 = blockRow + mw * 32 + t * 16 + lr;
            #pragma unroll
            for (int j = 0; j < 4; j++) {
                int col = colBase + nw * 32 + j * 8 + lc;
                if (row0 < nrows) {
                    float2 s = *(const float2*)&extra[(size_t)row0 * 256 + col];
                    part[t][0] += comb(hh[t][j][0], md[t][j][0], ll[t][j][0]) * s.x
                                + comb(hh[t][j][1], md[t][j][1], ll[t][j][1]) * s.y;
                }
                if (row0 + 8 < nrows) {
                    float2 s = *(const float2*)&extra[(size_t)(row0 + 8) * 256 + col];
                    part[t][1] += comb(hh[t][j][2], md[t][j][2], ll[t][j][2]) * s.x
                                + comb(hh[t][j][3], md[t][j][3], ll[t][j][3]) * s.y;
                }
            }
        }
        #pragma unroll
        for (int t = 0; t < 2; t++)
            #pragma unroll
            for (int h = 0; h < 2; h++) {
                part[t][h] += __shfl_xor_sync(0xffffffffu, part[t][h], 1);
                part[t][h] += __shfl_xor_sync(0xffffffffu, part[t][h], 2);
            }
        __syncthreads();                 // stage reads done before smem reuse
        float* red = (float*)smem;       // [64][2]
        if ((lane & 3) == 0) {
            #pragma unroll
            for (int t = 0; t < 2; t++) {
                red[(mw * 32 + t * 16 + lr) * 2 + nw]     = part[t][0];
                red[(mw * 32 + t * 16 + lr + 8) * 2 + nw] = part[t][1];
            }
        }
        __syncthreads();
        if (tid < 64) {
            int row = blockRow + tid;
            if (row < nrows) {
                float s = red[tid * 2] + red[tid * 2 + 1];
                asm volatile("red.global.add.f32 [%0], %1;"
                             :: "l"(g_sim + row), "f"(s) : "memory");
            }
        }
    } else if (MODE == 1) {
        #pragma unroll
        for (int t = 0; t < 2; t++)
            #pragma unroll
            for (int h = 0; h < 2; h++) {
                int row = blockRow + mw * 32 + t * 16 + lr + h * 8;
                if (row >= nrows) continue;
                #pragma unroll
                for (int j = 0; j < 4; j++) {
                    int col = colBase + nw * 32 + j * 8 + lc;
                    float2 b = *(const float2*)&extra[col];
                    float2 o;
                    o.x = comb(hh[t][j][2 * h + 0], md[t][j][2 * h + 0], ll[t][j][2 * h + 0]) + b.x;
                    o.y = comb(hh[t][j][2 * h + 1], md[t][j][2 * h + 1], ll[t][j][2 * h + 1]) + b.y;
                    *(float2*)&g_D[(size_t)row * 256 + col] = o;
                }
            }
    } else {
        #pragma unroll
        for (int t = 0; t < 2; t++)
            #pragma unroll
            for (int h = 0; h < 2; h++) {
                int row = blockRow + mw * 32 + t * 16 + lr + h * 8;
                if (row >= nrows) continue;
                int uid = ids[row];
                const float* Dr = g_D + (size_t)uid * 256;
                #pragma unroll
                for (int j = 0; j < 4; j++) {
                    int col = colBase + nw * 32 + j * 8 + lc;
                    float2 d = *(const float2*)&Dr[col];
                    float2 o;
                    o.x = fmaxf(comb(hh[t][j][2 * h + 0], md[t][j][2 * h + 0], ll[t][j][2 * h + 0]) + d.x, 0.0f);
                    o.y = fmaxf(comb(hh[t][j][2 * h + 1], md[t][j][2 * h + 1], ll[t][j][2 * h + 1]) + d.y, 0.0f);
                    *(float2*)&outp[(size_t)row * 256 + col] = o;
                }
            }
    }
}

// ---------------- launch ----------------------------------------------------------
extern "C" void kernel_launch(void* const* d_in, const int* in_sizes, int n_in,
                              void* d_out, int out_size) {
    const float* sess = (const float*)d_in[0];
    const float* ue   = (const float*)d_in[1];
    const int*   ids  = (const int*)d_in[2];   // JAX x64 disabled: int32
    const float* Wq   = (const float*)d_in[3];
    const float* Wk   = (const float*)d_in[4];
    const float* Wv   = (const float*)d_in[5];
    const float* W1   = (const float*)d_in[6];
    const float* b1   = (const float*)d_in[7];
    float*       out  = (float*)d_out;
    int N = in_sizes[0] / HH;   // 200000

    static bool attr_set = false;
    if (!attr_set) {
        cudaFuncSetAttribute(k_mma8<0>, cudaFuncAttributeMaxDynamicSharedMemorySize, NSTG * STG);
        cudaFuncSetAttribute(k_mma8<1>, cudaFuncAttributeMaxDynamicSharedMemorySize, NSTG * STG);
        cudaFuncSetAttribute(k_mma8<2>, cudaFuncAttributeMaxDynamicSharedMemorySize, NSTG * STG);
        attr_set = true;
    }

    dim3 gBig(4, (N + BM - 1) / BM);
    dim3 gU(4, (UU + BM - 1) / BM);
    k_zero<<<(NN + 255) / 256, 256>>>();
    k_prepT<<<dim3(8, 8, 2), 256>>>(Wq, Wk, Wv, W1);
    k_prepBt<<<256, 256>>>(W1);
    k_cvt8<<<N * (HH / 4) / 256, 256>>>((const float4*)ue);
    k_hist<<<(N + 255) / 256, 256>>>(ids, N);
    k_scan<<<1, 256>>>();
    k_fill<<<(N + 255) / 256, 256>>>(ids, N);
    k_mma8<0><<<gBig, 128, NSTG * STG>>>(sess, ids, nullptr, N);
    k_gather<<<(UU + 3) / 4, 256>>>(ue);
    k_mma8<1><<<gU, 128, NSTG * STG>>>(b1, nullptr, nullptr, UU);
    k_mma8<2><<<gBig, 128, NSTG * STG>>>(nullptr, ids, out, N);
}

// round 11
// speedup vs baseline: 2.4918x; 2.4918x over previous
#include <cuda_runtime.h>
#include <cuda_bf16.h>
#include <cstdint>

#define NN 200000
#define UU 20000
#define HH 256

#define BM 64
#define BN 64
#define BK 32
#define AH_OFF 0
#define AL_OFF 4096
#define BH_OFF 8192
#define BL_OFF 12288
#define STAGE_BYTES 16384
#define NSTG 3

// ---------------- scratch (device globals) -------------------------------------
__device__ __align__(16) __nv_bfloat16 g_Ah[(size_t)NN * HH];
__device__ __align__(16) __nv_bfloat16 g_Al[(size_t)NN * HH];
__device__ __align__(16) __nv_bfloat16 g_Wh[(size_t)UU * HH];   // normalized ws hi/lo
__device__ __align__(16) __nv_bfloat16 g_Wl[(size_t)UU * HH];
__device__ __align__(16) __nv_bfloat16 g_Mth [HH * HH], g_Mtl [HH * HH];  // M^T  hi/lo (n-major)
__device__ __align__(16) __nv_bfloat16 g_C1th[HH * HH], g_C1tl[HH * HH];  // C1^T hi/lo
__device__ __align__(16) __nv_bfloat16 g_Bth [HH * HH], g_Btl [HH * HH];  // W1[:,H:]  (n-major) hi/lo
__device__ __align__(16) float    g_D  [UU * HH];
__device__ __align__(16) float    g_sim[NN];
__device__ __align__(16) unsigned g_smax[UU];
__device__ int g_list[NN];          // CSR row lists
__device__ int g_off [UU + 1];
__device__ int g_cnt [UU];
__device__ int g_cnt2[UU];

// ---------------- helpers -------------------------------------------------------
__device__ __forceinline__ unsigned fenc(float f) {
    unsigned u = __float_as_uint(f);
    return (u & 0x80000000u) ? ~u : (u | 0x80000000u);
}
__device__ __forceinline__ float fdec(unsigned u) {
    return (u & 0x80000000u) ? __uint_as_float(u & 0x7FFFFFFFu) : __uint_as_float(~u);
}
__device__ __forceinline__ void ldsm4(uint32_t* r, uint32_t addr) {
    asm volatile("ldmatrix.sync.aligned.m8n8.x4.shared.b16 {%0,%1,%2,%3}, [%4];"
                 : "=r"(r[0]), "=r"(r[1]), "=r"(r[2]), "=r"(r[3]) : "r"(addr));
}
__device__ __forceinline__ void mma16816(float* c, const uint32_t* a, const uint32_t* b) {
    asm volatile("mma.sync.aligned.m16n8k16.row.col.f32.bf16.bf16.f32 "
                 "{%0,%1,%2,%3}, {%4,%5,%6,%7}, {%8,%9}, {%0,%1,%2,%3};"
                 : "+f"(c[0]), "+f"(c[1]), "+f"(c[2]), "+f"(c[3])
                 : "r"(a[0]), "r"(a[1]), "r"(a[2]), "r"(a[3]), "r"(b[0]), "r"(b[1]));
}
__device__ __forceinline__ void cpa16(uint32_t dst, const void* src, bool v) {
    int sz = v ? 16 : 0;
    asm volatile("cp.async.cg.shared.global [%0], [%1], 16, %2;"
                 :: "r"(dst), "l"(src), "r"(sz));
}
// swizzled byte offset of (row, 16B-chunk ch) in a 64B-stride tile
__device__ __forceinline__ uint32_t swz(int row, int ch) {
    return (uint32_t)(row * 64 + ((ch ^ ((row >> 1) & 3)) * 16));
}

// ---------------- init scratch -------------------------------------------------
__global__ void k_zero() {
    int idx = blockIdx.x * 256 + threadIdx.x;
    if (idx < NN) g_sim[idx] = 0.0f;
    if (idx < UU) { g_cnt[idx] = 0; g_cnt2[idx] = 0; g_smax[idx] = 0u; }
}

// ---------------- CSR build: hist -> scan -> fill --------------------------------
__global__ void k_hist(const int* __restrict__ ids, int n) {
    int i = blockIdx.x * 256 + threadIdx.x;
    if (i < n) atomicAdd(&g_cnt[ids[i]], 1);
}
__global__ void k_scan() {             // single block, 256 threads
    __shared__ int ps[256];
    const int C = (UU + 255) / 256;    // 79
    int t = threadIdx.x;
    int s = 0;
    for (int j = 0; j < C; j++) { int i = t * C + j; if (i < UU) s += g_cnt[i]; }
    ps[t] = s;
    __syncthreads();
    int acc = 0;
    for (int j = 0; j < t; j++) acc += ps[j];
    int run = acc;
    for (int j = 0; j < C; j++) {
        int i = t * C + j;
        if (i < UU) { g_off[i] = run; run += g_cnt[i]; }
    }
    if (t == 255) g_off[UU] = run;
}
__global__ void k_fill(const int* __restrict__ ids, int n) {
    int i = blockIdx.x * 256 + threadIdx.x;
    if (i < n) {
        int uid = ids[i];
        int pos = g_off[uid] + atomicAdd(&g_cnt2[uid], 1);
        g_list[pos] = i;
    }
}

// ---------------- coalesced precompute GEMMs -----------------------------------
// z==0: M[a,t]  = Wq[a,:]·Wk[t,:]      -> g_Mth/l [t*256+a]
// z==1: C1[a,t] = Wv[a,:]·W1[t,0:256]  -> g_C1th/l[t*256+a]
__global__ void k_prepT(const float* __restrict__ Wq, const float* __restrict__ Wk,
                        const float* __restrict__ Wv, const float* __restrict__ W1) {
    __shared__ float As[32 * 129];
    __shared__ float Bs[32 * 129];
    int z = blockIdx.z;
    int tid = threadIdx.x;
    int abase = blockIdx.y * 32;
    int tbase = blockIdx.x * 32;
    const float* Ag = z ? Wv : Wq;
    int tx = tid & 31, ty = tid >> 5;
    float acc[4] = {0.f, 0.f, 0.f, 0.f};

    for (int kt = 0; kt < 256; kt += 128) {
        #pragma unroll
        for (int i = 0; i < 16; i++) {
            int f = tid + i * 256;
            int r = f >> 7, c = f & 127;
            As[r * 129 + c] = Ag[(abase + r) * 256 + kt + c];
            Bs[r * 129 + c] = z ? W1[(tbase + r) * 512 + kt + c]
                                : Wk[(tbase + r) * 256 + kt + c];
        }
        __syncthreads();
        #pragma unroll 4
        for (int k = 0; k < 128; k++) {
            float av = As[tx * 129 + k];
            #pragma unroll
            for (int j = 0; j < 4; j++) acc[j] += av * Bs[(ty + 8 * j) * 129 + k];
        }
        __syncthreads();
    }
    int a = abase + tx;
    #pragma unroll
    for (int j = 0; j < 4; j++) {
        int t = tbase + ty + 8 * j;
        __nv_bfloat16 h = __float2bfloat16(acc[j]);
        __nv_bfloat16 l = __float2bfloat16(acc[j] - __bfloat162float(h));
        if (z == 0) { g_Mth [t * 256 + a] = h; g_Mtl [t * 256 + a] = l; }
        else        { g_C1th[t * 256 + a] = h; g_C1tl[t * 256 + a] = l; }
    }
}

// Bt (n-major, bf16 hi/lo): g_Bth[j*256+k] = W1[j*512+256+k]
__global__ void k_prepBt(const float* __restrict__ W1) {
    int j = blockIdx.x, k = threadIdx.x;
    float v = W1[j * 512 + 256 + k];
    __nv_bfloat16 h = __float2bfloat16(v);
    g_Bth[j * 256 + k] = h;
    g_Btl[j * 256 + k] = __float2bfloat16(v - __bfloat162float(h));
}

// ---------------- ue fp32 -> bf16 hi/lo split -------------------------------------
__global__ void k_cvt(const float4* __restrict__ src) {
    size_t i = (size_t)blockIdx.x * 256 + threadIdx.x;
    float4 v = src[i];
    __nv_bfloat16 h0 = __float2bfloat16(v.x), h1 = __float2bfloat16(v.y);
    __nv_bfloat16 h2 = __float2bfloat16(v.z), h3 = __float2bfloat16(v.w);
    __nv_bfloat162* H2 = (__nv_bfloat162*)g_Ah;
    H2[i * 2 + 0] = __halves2bfloat162(h0, h1);
    H2[i * 2 + 1] = __halves2bfloat162(h2, h3);
    __nv_bfloat16 l0 = __float2bfloat16(v.x - __bfloat162float(h0));
    __nv_bfloat16 l1 = __float2bfloat16(v.y - __bfloat162float(h1));
    __nv_bfloat16 l2 = __float2bfloat16(v.z - __bfloat162float(h2));
    __nv_bfloat16 l3 = __float2bfloat16(v.w - __bfloat162float(h3));
    __nv_bfloat162* L2 = (__nv_bfloat162*)g_Al;
    L2[i * 2 + 0] = __halves2bfloat162(l0, l1);
    L2[i * 2 + 1] = __halves2bfloat162(l2, l3);
}

// ---------------- softmax: segment max, exp, 1-pass gather -----------------------
__global__ void k_smax(const int* __restrict__ ids, int n) {
    int i = blockIdx.x * 256 + threadIdx.x;
    if (i < n) atomicMax(&g_smax[ids[i]], fenc(g_sim[i]));
}
__global__ void k_exp(const int* __restrict__ ids, int n) {
    int i = blockIdx.x * 256 + threadIdx.x;
    if (i < n) g_sim[i] = expf(g_sim[i] - fdec(g_smax[ids[i]]));
}
// block = 256 threads = 4 uids x 64 lanes; single pass over CSR rows
__global__ void k_gather(const float* __restrict__ ue) {
    int u    = blockIdx.x * 4 + (threadIdx.x >> 6);
    int lane = threadIdx.x & 63;
    if (u >= UU) return;
    int s = g_off[u], e = g_off[u + 1];

    float den = 0.0f;
    float4 acc = make_float4(0.f, 0.f, 0.f, 0.f);
    for (int r = s; r < e; r++) {
        int row = g_list[r];
        float ev = g_sim[row];                 // precomputed exp
        den += ev;
        float4 v = *(const float4*)&ue[(size_t)row * 256 + lane * 4];
        acc.x += ev * v.x; acc.y += ev * v.y; acc.z += ev * v.z; acc.w += ev * v.w;
    }
    float inv = (e > s) ? (1.0f / den) : 0.0f;
    acc.x *= inv; acc.y *= inv; acc.z *= inv; acc.w *= inv;

    __nv_bfloat16 h0 = __float2bfloat16(acc.x), h1 = __float2bfloat16(acc.y);
    __nv_bfloat16 h2 = __float2bfloat16(acc.z), h3 = __float2bfloat16(acc.w);
    __nv_bfloat162* H2 = (__nv_bfloat162*)&g_Wh[(size_t)u * 256 + lane * 4];
    H2[0] = __halves2bfloat162(h0, h1);
    H2[1] = __halves2bfloat162(h2, h3);
    __nv_bfloat16 l0 = __float2bfloat16(acc.x - __bfloat162float(h0));
    __nv_bfloat16 l1 = __float2bfloat16(acc.y - __bfloat162float(h1));
    __nv_bfloat16 l2 = __float2bfloat16(acc.z - __bfloat162float(h2));
    __nv_bfloat16 l3 = __float2bfloat16(acc.w - __bfloat162float(h3));
    __nv_bfloat162* L2 = (__nv_bfloat162*)&g_Wl[(size_t)u * 256 + lane * 4];
    L2[0] = __halves2bfloat162(l0, l1);
    L2[1] = __halves2bfloat162(l2, l3);
}

// ---------------- tensor-core GEMM (split-bf16, BM=64 BN=64, 3-stage, 4 CTA/SM) --
// grid = (4, rowBlocks): blockIdx.x = 64-col quarter (co-resident quarters share A)
// MODE 0: g_sim[row] += partial rowsum((A @ M) .* sess)               (A = ue)
// MODE 1: g_D = wsn @ Bt + b1                                          (A = wsn, extra = b1)
// MODE 2: out = relu(A @ C1 + g_D[ids])                                (A = ue)
template<int MODE>
__global__ __launch_bounds__(128, 4)
void k_mma(const float* __restrict__ extra, const int* __restrict__ ids,
           float* __restrict__ outp, int nrows) {
    extern __shared__ __align__(16) char smem[];
    uint32_t sbase = (uint32_t)__cvta_generic_to_shared(smem);
    const int tid  = threadIdx.x;
    const int lane = tid & 31;
    const int wid  = tid >> 5;                 // 0..3
    const int mw = wid >> 1, nw = wid & 1;     // 2 x 2 warp grid, warp tile 32x32
    const int blockRow = blockIdx.y * BM;
    const int colBase  = blockIdx.x * BN;

    const __nv_bfloat16* Ahp = (MODE == 1) ? g_Wh : g_Ah;
    const __nv_bfloat16* Alp = (MODE == 1) ? g_Wl : g_Al;
    const __nv_bfloat16* Bth = (MODE == 0) ? g_Mth : ((MODE == 1) ? g_Bth : g_C1th);
    const __nv_bfloat16* Btl = (MODE == 0) ? g_Mtl : ((MODE == 1) ? g_Btl : g_C1tl);

    float acc[2][4][4];
    #pragma unroll
    for (int t = 0; t < 2; t++)
        #pragma unroll
        for (int j = 0; j < 4; j++)
            #pragma unroll
            for (int c = 0; c < 4; c++) acc[t][j][c] = 0.0f;

    // ---- async tile loader (stage s, k-tile kt): 8 cpa16 per thread ----
    auto load_stage = [&](int kt, int s) {
        uint32_t db = sbase + (uint32_t)s * STAGE_BYTES;
        #pragma unroll
        for (int l = 0; l < 2; l++) {
            int u = tid + l * 128;
            int r = u >> 2, ch = u & 3;
            uint32_t dst = swz(r, ch);
            // A hi/lo: 64 rows x 4 chunks
            int grow = blockRow + r;
            bool v = grow < nrows;
            size_t ga = (size_t)(v ? grow : 0) * HH + kt * BK + ch * 8;
            cpa16(db + AH_OFF + dst, Ahp + ga, v);
            cpa16(db + AL_OFF + dst, Alp + ga, v);
            // B hi/lo: 64 rows x 4 chunks
            size_t gb = (size_t)(colBase + r) * HH + kt * BK + ch * 8;
            cpa16(db + BH_OFF + dst, Bth + gb, true);
            cpa16(db + BL_OFF + dst, Btl + gb, true);
        }
        asm volatile("cp.async.commit_group;" ::: "memory");
    };

    load_stage(0, 0);
    load_stage(1, 1);

    const int NKT = HH / BK;   // 8
    for (int kt = 0; kt < NKT; kt++) {
        if (kt < NKT - 1) asm volatile("cp.async.wait_group 1;" ::: "memory");
        else              asm volatile("cp.async.wait_group 0;" ::: "memory");
        __syncthreads();                                     // stage kt%3 ready; (kt+2)%3 drained
        if (kt + 2 < NKT) load_stage(kt + 2, (kt + 2) % NSTG);   // eager refill (lookahead 2)

        uint32_t sb = sbase + (uint32_t)(kt % NSTG) * STAGE_BYTES;
        #pragma unroll
        for (int k16 = 0; k16 < BK; k16 += 16) {
            uint32_t ah[2][4], al[2][4];
            #pragma unroll
            for (int t = 0; t < 2; t++) {
                int arow = mw * 32 + t * 16 + (lane & 15);
                int cb = (k16 >> 3) + (lane >> 4);
                uint32_t ao = swz(arow, cb);
                ldsm4(ah[t], sb + AH_OFF + ao);
                ldsm4(al[t], sb + AL_OFF + ao);
            }
            #pragma unroll
            for (int p = 0; p < 2; p++) {
                int brow = nw * 32 + p * 16 + (lane & 7) + ((lane >> 4) << 3);
                int cb = (k16 >> 3) + ((lane >> 3) & 1);
                uint32_t bo = swz(brow, cb);
                uint32_t bh[4], bl[4];
                ldsm4(bh, sb + BH_OFF + bo);
                ldsm4(bl, sb + BL_OFF + bo);
                #pragma unroll
                for (int t = 0; t < 2; t++)
                    #pragma unroll
                    for (int q = 0; q < 2; q++)
                        mma16816(acc[t][p * 2 + q], ah[t], &bh[2 * q]);
                #pragma unroll
                for (int t = 0; t < 2; t++)
                    #pragma unroll
                    for (int q = 0; q < 2; q++)
                        mma16816(acc[t][p * 2 + q], ah[t], &bl[2 * q]);
                #pragma unroll
                for (int t = 0; t < 2; t++)
                    #pragma unroll
                    for (int q = 0; q < 2; q++)
                        mma16816(acc[t][p * 2 + q], al[t], &bh[2 * q]);
            }
        }
    }

    const int lr = lane >> 2;           // 0..7
    const int lc = (lane & 3) * 2;      // 0,2,4,6

    if (MODE == 0) {
        float part[2][2] = {{0.f, 0.f}, {0.f, 0.f}};
        #pragma unroll
        for (int t = 0; t < 2; t++) {
            int row0 = blockRow + mw * 32 + t * 16 + lr;
            #pragma unroll
            for (int j = 0; j < 4; j++) {
                int col = colBase + nw * 32 + j * 8 + lc;
                if (row0 < nrows) {
                    float2 s = *(const float2*)&extra[(size_t)row0 * 256 + col];
                    part[t][0] += acc[t][j][0] * s.x + acc[t][j][1] * s.y;
                }
                if (row0 + 8 < nrows) {
                    float2 s = *(const float2*)&extra[(size_t)(row0 + 8) * 256 + col];
                    part[t][1] += acc[t][j][2] * s.x + acc[t][j][3] * s.y;
                }
            }
        }
        #pragma unroll
        for (int t = 0; t < 2; t++)
            #pragma unroll
            for (int h = 0; h < 2; h++) {
                part[t][h] += __shfl_xor_sync(0xffffffffu, part[t][h], 1);
                part[t][h] += __shfl_xor_sync(0xffffffffu, part[t][h], 2);
            }
        __syncthreads();                 // all smem reads done before reuse
        float* red = (float*)smem;       // [64][2]
        if ((lane & 3) == 0) {
            #pragma unroll
            for (int t = 0; t < 2; t++) {
                red[(mw * 32 + t * 16 + lr) * 2 + nw]     = part[t][0];
                red[(mw * 32 + t * 16 + lr + 8) * 2 + nw] = part[t][1];
            }
        }
        __syncthreads();
        if (tid < 64) {
            int row = blockRow + tid;
            if (row < nrows) {
                float s = red[tid * 2] + red[tid * 2 + 1];
                asm volatile("red.global.add.f32 [%0], %1;"
                             :: "l"(g_sim + row), "f"(s) : "memory");
            }
        }
    } else if (MODE == 1) {
        #pragma unroll
        for (int t = 0; t < 2; t++)
            #pragma unroll
            for (int h = 0; h < 2; h++) {
                int row = blockRow + mw * 32 + t * 16 + lr + h * 8;
                if (row >= nrows) continue;
                #pragma unroll
                for (int j = 0; j < 4; j++) {
                    int col = colBase + nw * 32 + j * 8 + lc;
                    float2 b = *(const float2*)&extra[col];
                    float2 o;
                    o.x = acc[t][j][2 * h + 0] + b.x;
                    o.y = acc[t][j][2 * h + 1] + b.y;
                    *(float2*)&g_D[(size_t)row * 256 + col] = o;
                }
            }
    } else {
        #pragma unroll
        for (int t = 0; t < 2; t++)
            #pragma unroll
            for (int h = 0; h < 2; h++) {
                int row = blockRow + mw * 32 + t * 16 + lr + h * 8;
                if (row >= nrows) continue;
                int uid = ids[row];
                const float* Dr = g_D + (size_t)uid * 256;
                #pragma unroll
                for (int j = 0; j < 4; j++) {
                    int col = colBase + nw * 32 + j * 8 + lc;
                    float2 d = *(const float2*)&Dr[col];
                    float2 o;
                    o.x = fmaxf(acc[t][j][2 * h + 0] + d.x, 0.0f);
                    o.y = fmaxf(acc[t][j][2 * h + 1] + d.y, 0.0f);
                    *(float2*)&outp[(size_t)row * 256 + col] = o;
                }
            }
    }
}

// ---------------- launch ----------------------------------------------------------
extern "C" void kernel_launch(void* const* d_in, const int* in_sizes, int n_in,
                              void* d_out, int out_size) {
    const float* sess = (const float*)d_in[0];
    const float* ue   = (const float*)d_in[1];
    const int*   ids  = (const int*)d_in[2];   // JAX x64 disabled: int32
    const float* Wq   = (const float*)d_in[3];
    const float* Wk   = (const float*)d_in[4];
    const float* Wv   = (const float*)d_in[5];
    const float* W1   = (const float*)d_in[6];
    const float* b1   = (const float*)d_in[7];
    float*       out  = (float*)d_out;
    int N = in_sizes[0] / HH;   // 200000

    static bool attr_set = false;
    if (!attr_set) {
        cudaFuncSetAttribute(k_mma<0>, cudaFuncAttributeMaxDynamicSharedMemorySize, NSTG * STAGE_BYTES);
        cudaFuncSetAttribute(k_mma<1>, cudaFuncAttributeMaxDynamicSharedMemorySize, NSTG * STAGE_BYTES);
        cudaFuncSetAttribute(k_mma<2>, cudaFuncAttributeMaxDynamicSharedMemorySize, NSTG * STAGE_BYTES);
        attr_set = true;
    }

    dim3 gBig(4, (N + BM - 1) / BM);
    dim3 gU(4, (UU + BM - 1) / BM);
    k_zero<<<(NN + 255) / 256, 256>>>();
    k_prepT<<<dim3(8, 8, 2), 256>>>(Wq, Wk, Wv, W1);
    k_prepBt<<<256, 256>>>(W1);
    k_cvt<<<N * (HH / 4) / 256, 256>>>((const float4*)ue);
    k_hist<<<(N + 255) / 256, 256>>>(ids, N);
    k_scan<<<1, 256>>>();
    k_fill<<<(N + 255) / 256, 256>>>(ids, N);
    k_mma<0><<<gBig, 128, NSTG * STAGE_BYTES>>>(sess, ids, nullptr, N);
    k_smax<<<(N + 255) / 256, 256>>>(ids, N);
    k_exp<<<(N + 255) / 256, 256>>>(ids, N);
    k_gather<<<(UU + 3) / 4, 256>>>(ue);
    k_mma<1><<<gU, 128, NSTG * STAGE_BYTES>>>(b1, nullptr, nullptr, UU);
    k_mma<2><<<gBig, 128, NSTG * STAGE_BYTES>>>(nullptr, ids, out, N);
}

// round 12
// speedup vs baseline: 2.5909x; 1.0398x over previous
#include <cuda_runtime.h>
#include <cuda_bf16.h>
#include <cstdint>

#define NN 200000
#define UU 20000
#define HH 256

#define BM 64
#define BN 128
#define BK 32
#define AH_OFF 0
#define AL_OFF 4096
#define BH_OFF 8192
#define BL_OFF 16384
#define STAGE_BYTES 24576
#define NSTAGE 2

// ---------------- scratch (device globals) -------------------------------------
__device__ __align__(16) __nv_bfloat16 g_Ah[(size_t)NN * HH];
__device__ __align__(16) __nv_bfloat16 g_Al[(size_t)NN * HH];
__device__ __align__(16) __nv_bfloat16 g_Wh[(size_t)UU * HH];   // normalized ws hi/lo
__device__ __align__(16) __nv_bfloat16 g_Wl[(size_t)UU * HH];
__device__ __align__(16) __nv_bfloat16 g_Mth [HH * HH], g_Mtl [HH * HH];  // M^T  hi/lo (n-major)
__device__ __align__(16) __nv_bfloat16 g_C1th[HH * HH], g_C1tl[HH * HH];  // C1^T hi/lo
__device__ __align__(16) __nv_bfloat16 g_Bth [HH * HH], g_Btl [HH * HH];  // W1[:,H:]  (n-major) hi/lo
__device__ __align__(16) float    g_D  [UU * HH];
__device__ __align__(16) float    g_sim[NN];
__device__ __align__(16) unsigned g_smax[UU];
__device__ int g_list[NN];          // CSR row lists
__device__ int g_off [UU + 1];
__device__ int g_cnt [UU];
__device__ int g_cnt2[UU];

// ---------------- helpers -------------------------------------------------------
__device__ __forceinline__ unsigned fenc(float f) {
    unsigned u = __float_as_uint(f);
    return (u & 0x80000000u) ? ~u : (u | 0x80000000u);
}
__device__ __forceinline__ float fdec(unsigned u) {
    return (u & 0x80000000u) ? __uint_as_float(u & 0x7FFFFFFFu) : __uint_as_float(~u);
}
__device__ __forceinline__ void ldsm4(uint32_t* r, uint32_t addr) {
    asm volatile("ldmatrix.sync.aligned.m8n8.x4.shared.b16 {%0,%1,%2,%3}, [%4];"
                 : "=r"(r[0]), "=r"(r[1]), "=r"(r[2]), "=r"(r[3]) : "r"(addr));
}
__device__ __forceinline__ void mma16816(float* c, const uint32_t* a, const uint32_t* b) {
    asm volatile("mma.sync.aligned.m16n8k16.row.col.f32.bf16.bf16.f32 "
                 "{%0,%1,%2,%3}, {%4,%5,%6,%7}, {%8,%9}, {%0,%1,%2,%3};"
                 : "+f"(c[0]), "+f"(c[1]), "+f"(c[2]), "+f"(c[3])
                 : "r"(a[0]), "r"(a[1]), "r"(a[2]), "r"(a[3]), "r"(b[0]), "r"(b[1]));
}
__device__ __forceinline__ void cpa16(uint32_t dst, const void* src, bool v) {
    int sz = v ? 16 : 0;
    asm volatile("cp.async.cg.shared.global [%0], [%1], 16, %2;"
                 :: "r"(dst), "l"(src), "r"(sz));
}
// swizzled byte offset of (row, 16B-chunk ch) in a 64B-stride tile
__device__ __forceinline__ uint32_t swz(int row, int ch) {
    return (uint32_t)(row * 64 + ((ch ^ ((row >> 1) & 3)) * 16));
}

// ---------------- init scratch -------------------------------------------------
__global__ void k_zero() {
    int idx = blockIdx.x * 256 + threadIdx.x;
    if (idx < NN) g_sim[idx] = 0.0f;
    if (idx < UU) { g_cnt[idx] = 0; g_cnt2[idx] = 0; g_smax[idx] = 0u; }
}

// ---------------- CSR build: hist -> scan -> fill --------------------------------
__global__ void k_hist(const int* __restrict__ ids, int n) {
    int i = blockIdx.x * 256 + threadIdx.x;
    if (i < n) atomicAdd(&g_cnt[ids[i]], 1);
}
__global__ void k_scan() {             // single block, 256 threads
    __shared__ int ps[256];
    const int C = (UU + 255) / 256;    // 79
    int t = threadIdx.x;
    int s = 0;
    for (int j = 0; j < C; j++) { int i = t * C + j; if (i < UU) s += g_cnt[i]; }
    ps[t] = s;
    __syncthreads();
    int acc = 0;
    for (int j = 0; j < t; j++) acc += ps[j];
    int run = acc;
    for (int j = 0; j < C; j++) {
        int i = t * C + j;
        if (i < UU) { g_off[i] = run; run += g_cnt[i]; }
    }
    if (t == 255) g_off[UU] = run;
}
__global__ void k_fill(const int* __restrict__ ids, int n) {
    int i = blockIdx.x * 256 + threadIdx.x;
    if (i < n) {
        int uid = ids[i];
        int pos = g_off[uid] + atomicAdd(&g_cnt2[uid], 1);
        g_list[pos] = i;
    }
}

// ---------------- coalesced precompute GEMMs -----------------------------------
// z==0: M[a,t]  = Wq[a,:]·Wk[t,:]      -> g_Mth/l [t*256+a]
// z==1: C1[a,t] = Wv[a,:]·W1[t,0:256]  -> g_C1th/l[t*256+a]
__global__ void k_prepT(const float* __restrict__ Wq, const float* __restrict__ Wk,
                        const float* __restrict__ Wv, const float* __restrict__ W1) {
    __shared__ float As[32 * 129];
    __shared__ float Bs[32 * 129];
    int z = blockIdx.z;
    int tid = threadIdx.x;
    int abase = blockIdx.y * 32;
    int tbase = blockIdx.x * 32;
    const float* Ag = z ? Wv : Wq;
    int tx = tid & 31, ty = tid >> 5;
    float acc[4] = {0.f, 0.f, 0.f, 0.f};

    for (int kt = 0; kt < 256; kt += 128) {
        #pragma unroll
        for (int i = 0; i < 16; i++) {
            int f = tid + i * 256;
            int r = f >> 7, c = f & 127;
            As[r * 129 + c] = Ag[(abase + r) * 256 + kt + c];
            Bs[r * 129 + c] = z ? W1[(tbase + r) * 512 + kt + c]
                                : Wk[(tbase + r) * 256 + kt + c];
        }
        __syncthreads();
        #pragma unroll 4
        for (int k = 0; k < 128; k++) {
            float av = As[tx * 129 + k];
            #pragma unroll
            for (int j = 0; j < 4; j++) acc[j] += av * Bs[(ty + 8 * j) * 129 + k];
        }
        __syncthreads();
    }
    int a = abase + tx;
    #pragma unroll
    for (int j = 0; j < 4; j++) {
        int t = tbase + ty + 8 * j;
        __nv_bfloat16 h = __float2bfloat16(acc[j]);
        __nv_bfloat16 l = __float2bfloat16(acc[j] - __bfloat162float(h));
        if (z == 0) { g_Mth [t * 256 + a] = h; g_Mtl [t * 256 + a] = l; }
        else        { g_C1th[t * 256 + a] = h; g_C1tl[t * 256 + a] = l; }
    }
}

// Bt (n-major, bf16 hi/lo): g_Bth[j*256+k] = W1[j*512+256+k]
__global__ void k_prepBt(const float* __restrict__ W1) {
    int j = blockIdx.x, k = threadIdx.x;
    float v = W1[j * 512 + 256 + k];
    __nv_bfloat16 h = __float2bfloat16(v);
    g_Bth[j * 256 + k] = h;
    g_Btl[j * 256 + k] = __float2bfloat16(v - __bfloat162float(h));
}

// ---------------- ue fp32 -> bf16 hi/lo split -------------------------------------
__global__ void k_cvt(const float4* __restrict__ src) {
    size_t i = (size_t)blockIdx.x * 256 + threadIdx.x;
    float4 v = src[i];
    __nv_bfloat16 h0 = __float2bfloat16(v.x), h1 = __float2bfloat16(v.y);
    __nv_bfloat16 h2 = __float2bfloat16(v.z), h3 = __float2bfloat16(v.w);
    __nv_bfloat162* H2 = (__nv_bfloat162*)g_Ah;
    H2[i * 2 + 0] = __halves2bfloat162(h0, h1);
    H2[i * 2 + 1] = __halves2bfloat162(h2, h3);
    __nv_bfloat16 l0 = __float2bfloat16(v.x - __bfloat162float(h0));
    __nv_bfloat16 l1 = __float2bfloat16(v.y - __bfloat162float(h1));
    __nv_bfloat16 l2 = __float2bfloat16(v.z - __bfloat162float(h2));
    __nv_bfloat16 l3 = __float2bfloat16(v.w - __bfloat162float(h3));
    __nv_bfloat162* L2 = (__nv_bfloat162*)g_Al;
    L2[i * 2 + 0] = __halves2bfloat162(l0, l1);
    L2[i * 2 + 1] = __halves2bfloat162(l2, l3);
}

// ---------------- softmax: segment max, exp, 1-pass gather -----------------------
__global__ void k_smax(const int* __restrict__ ids, int n) {
    int i = blockIdx.x * 256 + threadIdx.x;
    if (i < n) atomicMax(&g_smax[ids[i]], fenc(g_sim[i]));
}
__global__ void k_exp(const int* __restrict__ ids, int n) {
    int i = blockIdx.x * 256 + threadIdx.x;
    if (i < n) g_sim[i] = expf(g_sim[i] - fdec(g_smax[ids[i]]));
}
// block = 256 threads = 4 uids x 64 lanes; single pass over CSR rows
__global__ void k_gather(const float* __restrict__ ue) {
    int u    = blockIdx.x * 4 + (threadIdx.x >> 6);
    int lane = threadIdx.x & 63;
    if (u >= UU) return;
    int s = g_off[u], e = g_off[u + 1];

    float den = 0.0f;
    float4 acc = make_float4(0.f, 0.f, 0.f, 0.f);
    for (int r = s; r < e; r++) {
        int row = g_list[r];
        float ev = g_sim[row];                 // precomputed exp
        den += ev;
        float4 v = *(const float4*)&ue[(size_t)row * 256 + lane * 4];
        acc.x += ev * v.x; acc.y += ev * v.y; acc.z += ev * v.z; acc.w += ev * v.w;
    }
    float inv = (e > s) ? (1.0f / den) : 0.0f;
    acc.x *= inv; acc.y *= inv; acc.z *= inv; acc.w *= inv;

    __nv_bfloat16 h0 = __float2bfloat16(acc.x), h1 = __float2bfloat16(acc.y);
    __nv_bfloat16 h2 = __float2bfloat16(acc.z), h3 = __float2bfloat16(acc.w);
    __nv_bfloat162* H2 = (__nv_bfloat162*)&g_Wh[(size_t)u * 256 + lane * 4];
    H2[0] = __halves2bfloat162(h0, h1);
    H2[1] = __halves2bfloat162(h2, h3);
    __nv_bfloat16 l0 = __float2bfloat16(acc.x - __bfloat162float(h0));
    __nv_bfloat16 l1 = __float2bfloat16(acc.y - __bfloat162float(h1));
    __nv_bfloat16 l2 = __float2bfloat16(acc.z - __bfloat162float(h2));
    __nv_bfloat16 l3 = __float2bfloat16(acc.w - __bfloat162float(h3));
    __nv_bfloat162* L2 = (__nv_bfloat162*)&g_Wl[(size_t)u * 256 + lane * 4];
    L2[0] = __halves2bfloat162(l0, l1);
    L2[1] = __halves2bfloat162(l2, l3);
}

// ---------------- tensor-core GEMM (split-bf16, BM=64 BN=128, 4 CTA/SM) ----------
// grid = (2, rowBlocks): blockIdx.x = 128-col half (co-resident halves share A in L2)
// MODE 0: g_sim[row] += partial rowsum((A @ M) .* sess)               (A = ue)
// MODE 1: g_D = wsn @ Bt + b1                                          (A = wsn, extra = b1)
// MODE 2: out = relu(A @ C1 + g_D[ids])                                (A = ue)
template<int MODE>
__global__ __launch_bounds__(128, 4)
void k_mma(const float* __restrict__ extra, const int* __restrict__ ids,
           float* __restrict__ outp, int nrows) {
    extern __shared__ __align__(16) char smem[];
    uint32_t sbase = (uint32_t)__cvta_generic_to_shared(smem);
    const int tid  = threadIdx.x;
    const int lane = tid & 31;
    const int wid  = tid >> 5;                 // 0..3
    const int mw = wid >> 1, nw = wid & 1;     // 2 x 2 warp grid, warp tile 32x64
    const int blockRow = blockIdx.y * BM;
    const int colBase  = blockIdx.x * BN;

    const __nv_bfloat16* Ahp = (MODE == 1) ? g_Wh : g_Ah;
    const __nv_bfloat16* Alp = (MODE == 1) ? g_Wl : g_Al;
    const __nv_bfloat16* Bth = (MODE == 0) ? g_Mth : ((MODE == 1) ? g_Bth : g_C1th);
    const __nv_bfloat16* Btl = (MODE == 0) ? g_Mtl : ((MODE == 1) ? g_Btl : g_C1tl);

    float acc[2][8][4];
    #pragma unroll
    for (int t = 0; t < 2; t++)
        #pragma unroll
        for (int j = 0; j < 8; j++)
            #pragma unroll
            for (int c = 0; c < 4; c++) acc[t][j][c] = 0.0f;

    // ---- async tile loader (stage s, k-tile kt): 12 cpa16 per thread ----
    auto load_stage = [&](int kt, int s) {
        uint32_t db = sbase + (uint32_t)s * STAGE_BYTES;
        #pragma unroll
        for (int l = 0; l < 2; l++) {           // A hi/lo: 64 rows x 4 chunks
            int u = tid + l * 128;
            int r = u >> 2, ch = u & 3;
            int grow = blockRow + r;
            bool v = grow < nrows;
            size_t ga = (size_t)(v ? grow : 0) * HH + kt * BK + ch * 8;
            uint32_t dst = swz(r, ch);
            cpa16(db + AH_OFF + dst, Ahp + ga, v);
            cpa16(db + AL_OFF + dst, Alp + ga, v);
        }
        #pragma unroll
        for (int l = 0; l < 4; l++) {           // B hi/lo: 128 rows x 4 chunks
            int u = tid + l * 128;
            int r = u >> 2, ch = u & 3;
            size_t gb = (size_t)(colBase + r) * HH + kt * BK + ch * 8;
            uint32_t dst = swz(r, ch);
            cpa16(db + BH_OFF + dst, Bth + gb, true);
            cpa16(db + BL_OFF + dst, Btl + gb, true);
        }
        asm volatile("cp.async.commit_group;" ::: "memory");
    };

    load_stage(0, 0);
    load_stage(1, 1);

    const int NKT = HH / BK;   // 8
    for (int kt = 0; kt < NKT; kt++) {
        if (kt < NKT - 1) asm volatile("cp.async.wait_group 1;" ::: "memory");
        else              asm volatile("cp.async.wait_group 0;" ::: "memory");
        __syncthreads();

        uint32_t sb = sbase + (uint32_t)(kt & 1) * STAGE_BYTES;
        #pragma unroll
        for (int k16 = 0; k16 < BK; k16 += 16) {
            uint32_t ah[2][4], al[2][4];
            #pragma unroll
            for (int t = 0; t < 2; t++) {
                int arow = mw * 32 + t * 16 + (lane & 15);
                int cb = (k16 >> 3) + (lane >> 4);
                uint32_t ao = swz(arow, cb);
                ldsm4(ah[t], sb + AH_OFF + ao);
                ldsm4(al[t], sb + AL_OFF + ao);
            }
            #pragma unroll
            for (int p = 0; p < 4; p++) {
                int brow = nw * 64 + p * 16 + (lane & 7) + ((lane >> 4) << 3);
                int cb = (k16 >> 3) + ((lane >> 3) & 1);
                uint32_t bo = swz(brow, cb);
                uint32_t bh[4], bl[4];
                ldsm4(bh, sb + BH_OFF + bo);
                ldsm4(bl, sb + BL_OFF + bo);
                #pragma unroll
                for (int t = 0; t < 2; t++)
                    #pragma unroll
                    for (int q = 0; q < 2; q++)
                        mma16816(acc[t][p * 2 + q], ah[t], &bh[2 * q]);
                #pragma unroll
                for (int t = 0; t < 2; t++)
                    #pragma unroll
                    for (int q = 0; q < 2; q++)
                        mma16816(acc[t][p * 2 + q], ah[t], &bl[2 * q]);
                #pragma unroll
                for (int t = 0; t < 2; t++)
                    #pragma unroll
                    for (int q = 0; q < 2; q++)
                        mma16816(acc[t][p * 2 + q], al[t], &bh[2 * q]);
            }
        }
        __syncthreads();                                    // stage fully consumed
        if (kt + 2 < NKT) load_stage(kt + 2, kt & 1);       // refill same stage
    }

    const int lr = lane >> 2;           // 0..7
    const int lc = (lane & 3) * 2;      // 0,2,4,6

    if (MODE == 0) {
        float part[2][2] = {{0.f, 0.f}, {0.f, 0.f}};
        #pragma unroll
        for (int t = 0; t < 2; t++) {
            int row0 = blockRow + mw * 32 + t * 16 + lr;
            #pragma unroll
            for (int j = 0; j < 8; j++) {
                int col = colBase + nw * 64 + j * 8 + lc;
                if (row0 < nrows) {
                    float2 s = *(const float2*)&extra[(size_t)row0 * 256 + col];
                    part[t][0] += acc[t][j][0] * s.x + acc[t][j][1] * s.y;
                }
                if (row0 + 8 < nrows) {
                    float2 s = *(const float2*)&extra[(size_t)(row0 + 8) * 256 + col];
                    part[t][1] += acc[t][j][2] * s.x + acc[t][j][3] * s.y;
                }
            }
        }
        #pragma unroll
        for (int t = 0; t < 2; t++)
            #pragma unroll
            for (int h = 0; h < 2; h++) {
                part[t][h] += __shfl_xor_sync(0xffffffffu, part[t][h], 1);
                part[t][h] += __shfl_xor_sync(0xffffffffu, part[t][h], 2);
            }
        __syncthreads();                 // stage reads done before smem reuse
        float* red = (float*)smem;       // [64][2]
        if ((lane & 3) == 0) {
            #pragma unroll
            for (int t = 0; t < 2; t++) {
                red[(mw * 32 + t * 16 + lr) * 2 + nw]     = part[t][0];
                red[(mw * 32 + t * 16 + lr + 8) * 2 + nw] = part[t][1];
            }
        }
        __syncthreads();
        if (tid < 64) {
            int row = blockRow + tid;
            if (row < nrows) {
                float s = red[tid * 2] + red[tid * 2 + 1];
                asm volatile("red.global.add.f32 [%0], %1;"
                             :: "l"(g_sim + row), "f"(s) : "memory");
            }
        }
    } else if (MODE == 1) {
        #pragma unroll
        for (int t = 0; t < 2; t++)
            #pragma unroll
            for (int h = 0; h < 2; h++) {
                int row = blockRow + mw * 32 + t * 16 + lr + h * 8;
                if (row >= nrows) continue;
                #pragma unroll
                for (int j = 0; j < 8; j++) {
                    int col = colBase + nw * 64 + j * 8 + lc;
                    float2 b = *(const float2*)&extra[col];
                    float2 o;
                    o.x = acc[t][j][2 * h + 0] + b.x;
                    o.y = acc[t][j][2 * h + 1] + b.y;
                    *(float2*)&g_D[(size_t)row * 256 + col] = o;
                }
            }
    } else {
        #pragma unroll
        for (int t = 0; t < 2; t++)
            #pragma unroll
            for (int h = 0; h < 2; h++) {
                int row = blockRow + mw * 32 + t * 16 + lr + h * 8;
                if (row >= nrows) continue;
                int uid = ids[row];
                const float* Dr = g_D + (size_t)uid * 256;
                #pragma unroll
                for (int j = 0; j < 8; j++) {
                    int col = colBase + nw * 64 + j * 8 + lc;
                    float2 d = *(const float2*)&Dr[col];
                    float2 o;
                    o.x = fmaxf(acc[t][j][2 * h + 0] + d.x, 0.0f);
                    o.y = fmaxf(acc[t][j][2 * h + 1] + d.y, 0.0f);
                    *(float2*)&outp[(size_t)row * 256 + col] = o;
                }
            }
    }
}

// ---------------- launch ----------------------------------------------------------
extern "C" void kernel_launch(void* const* d_in, const int* in_sizes, int n_in,
                              void* d_out, int out_size) {
    const float* sess = (const float*)d_in[0];
    const float* ue   = (const float*)d_in[1];
    const int*   ids  = (const int*)d_in[2];   // JAX x64 disabled: int32
    const float* Wq   = (const float*)d_in[3];
    const float* Wk   = (const float*)d_in[4];
    const float* Wv   = (const float*)d_in[5];
    const float* W1   = (const float*)d_in[6];
    const float* b1   = (const float*)d_in[7];
    float*       out  = (float*)d_out;
    int N = in_sizes[0] / HH;   // 200000

    static bool attr_set = false;
    if (!attr_set) {
        cudaFuncSetAttribute(k_mma<0>, cudaFuncAttributeMaxDynamicSharedMemorySize, NSTAGE * STAGE_BYTES);
        cudaFuncSetAttribute(k_mma<1>, cudaFuncAttributeMaxDynamicSharedMemorySize, NSTAGE * STAGE_BYTES);
        cudaFuncSetAttribute(k_mma<2>, cudaFuncAttributeMaxDynamicSharedMemorySize, NSTAGE * STAGE_BYTES);
        attr_set = true;
    }

    dim3 gBig(2, (N + BM - 1) / BM);
    dim3 gU(2, (UU + BM - 1) / BM);
    k_zero<<<(NN + 255) / 256, 256>>>();
    k_prepT<<<dim3(8, 8, 2), 256>>>(Wq, Wk, Wv, W1);
    k_prepBt<<<256, 256>>>(W1);
    k_cvt<<<N * (HH / 4) / 256, 256>>>((const float4*)ue);
    k_hist<<<(N + 255) / 256, 256>>>(ids, N);
    k_scan<<<1, 256>>>();
    k_fill<<<(N + 255) / 256, 256>>>(ids, N);
    k_mma<0><<<gBig, 128, NSTAGE * STAGE_BYTES>>>(sess, ids, nullptr, N);
    k_smax<<<(N + 255) / 256, 256>>>(ids, N);
    k_exp<<<(N + 255) / 256, 256>>>(ids, N);
    k_gather<<<(UU + 3) / 4, 256>>>(ue);
    k_mma<1><<<gU, 128, NSTAGE * STAGE_BYTES>>>(b1, nullptr, nullptr, UU);
    k_mma<2><<<gBig, 128, NSTAGE * STAGE_BYTES>>>(nullptr, ids, out, N);
}

// round 13
// speedup vs baseline: 2.6164x; 1.0098x over previous
#include <cuda_runtime.h>
#include <cuda_bf16.h>
#include <cstdint>

#define NN 200000
#define UU 20000
#define HH 256

#define BM 64
#define BN 128
#define BK 32
#define AH_OFF 0
#define AL_OFF 4096
#define BH_OFF 8192
#define BL_OFF 16384
#define STAGE_BYTES 24576
#define NSTAGE 2

// ---------------- scratch (device globals) -------------------------------------
__device__ __align__(16) __nv_bfloat16 g_Mth [HH * HH], g_Mtl [HH * HH];  // M^T  hi/lo (n-major)
__device__ __align__(16) __nv_bfloat16 g_C1th[HH * HH], g_C1tl[HH * HH];  // C1^T hi/lo
__device__ __align__(16) __nv_bfloat16 g_Bth [HH * HH], g_Btl [HH * HH];  // W1[:,H:]  (n-major) hi/lo
__device__ __align__(16) float    g_wsn[UU * HH];   // normalized weighted sum (fp32)
__device__ __align__(16) float    g_D  [UU * HH];
__device__ __align__(16) float    g_sim[NN];
__device__ __align__(16) unsigned g_smax[UU];
__device__ int g_list[NN];          // CSR row lists
__device__ int g_off [UU + 1];
__device__ int g_cnt [UU];
__device__ int g_cnt2[UU];

// ---------------- helpers -------------------------------------------------------
__device__ __forceinline__ unsigned fenc(float f) {
    unsigned u = __float_as_uint(f);
    return (u & 0x80000000u) ? ~u : (u | 0x80000000u);
}
__device__ __forceinline__ float fdec(unsigned u) {
    return (u & 0x80000000u) ? __uint_as_float(u & 0x7FFFFFFFu) : __uint_as_float(~u);
}
__device__ __forceinline__ void ldsm4(uint32_t* r, uint32_t addr) {
    asm volatile("ldmatrix.sync.aligned.m8n8.x4.shared.b16 {%0,%1,%2,%3}, [%4];"
                 : "=r"(r[0]), "=r"(r[1]), "=r"(r[2]), "=r"(r[3]) : "r"(addr));
}
__device__ __forceinline__ void mma16816(float* c, const uint32_t* a, const uint32_t* b) {
    asm volatile("mma.sync.aligned.m16n8k16.row.col.f32.bf16.bf16.f32 "
                 "{%0,%1,%2,%3}, {%4,%5,%6,%7}, {%8,%9}, {%0,%1,%2,%3};"
                 : "+f"(c[0]), "+f"(c[1]), "+f"(c[2]), "+f"(c[3])
                 : "r"(a[0]), "r"(a[1]), "r"(a[2]), "r"(a[3]), "r"(b[0]), "r"(b[1]));
}
__device__ __forceinline__ void cpa16(uint32_t dst, const void* src, bool v) {
    int sz = v ? 16 : 0;
    asm volatile("cp.async.cg.shared.global [%0], [%1], 16, %2;"
                 :: "r"(dst), "l"(src), "r"(sz));
}
// swizzled byte offset of (row, 16B-chunk ch) in a 64B-stride tile
__device__ __forceinline__ uint32_t swz(int row, int ch) {
    return (uint32_t)(row * 64 + ((ch ^ ((row >> 1) & 3)) * 16));
}
// 2 fp32 -> packed bf16x2 hi and lo digits
__device__ __forceinline__ void split2(float x, float y, uint32_t& hi, uint32_t& lo) {
    __nv_bfloat16 h0 = __float2bfloat16(x), h1 = __float2bfloat16(y);
    __nv_bfloat162 hp = __halves2bfloat162(h0, h1);
    hi = *(uint32_t*)&hp;
    __nv_bfloat16 l0 = __float2bfloat16(x - __bfloat162float(h0));
    __nv_bfloat16 l1 = __float2bfloat16(y - __bfloat162float(h1));
    __nv_bfloat162 lp = __halves2bfloat162(l0, l1);
    lo = *(uint32_t*)&lp;
}

// ---------------- init scratch -------------------------------------------------
__global__ void k_zero() {
    int idx = blockIdx.x * 256 + threadIdx.x;
    if (idx < NN) g_sim[idx] = 0.0f;
    if (idx < UU) { g_cnt[idx] = 0; g_cnt2[idx] = 0; g_smax[idx] = 0u; }
}

// ---------------- CSR build: hist -> scan -> fill --------------------------------
__global__ void k_hist(const int* __restrict__ ids, int n) {
    int i = blockIdx.x * 256 + threadIdx.x;
    if (i < n) atomicAdd(&g_cnt[ids[i]], 1);
}
__global__ void k_scan() {             // single block, 256 threads
    __shared__ int ps[256];
    const int C = (UU + 255) / 256;    // 79
    int t = threadIdx.x;
    int s = 0;
    for (int j = 0; j < C; j++) { int i = t * C + j; if (i < UU) s += g_cnt[i]; }
    ps[t] = s;
    __syncthreads();
    int acc = 0;
    for (int j = 0; j < t; j++) acc += ps[j];
    int run = acc;
    for (int j = 0; j < C; j++) {
        int i = t * C + j;
        if (i < UU) { g_off[i] = run; run += g_cnt[i]; }
    }
    if (t == 255) g_off[UU] = run;
}
__global__ void k_fill(const int* __restrict__ ids, int n) {
    int i = blockIdx.x * 256 + threadIdx.x;
    if (i < n) {
        int uid = ids[i];
        int pos = g_off[uid] + atomicAdd(&g_cnt2[uid], 1);
        g_list[pos] = i;
    }
}

// ---------------- coalesced precompute GEMMs -----------------------------------
// z==0: M[a,t]  = Wq[a,:]·Wk[t,:]      -> g_Mth/l [t*256+a]
// z==1: C1[a,t] = Wv[a,:]·W1[t,0:256]  -> g_C1th/l[t*256+a]
__global__ void k_prepT(const float* __restrict__ Wq, const float* __restrict__ Wk,
                        const float* __restrict__ Wv, const float* __restrict__ W1) {
    __shared__ float As[32 * 129];
    __shared__ float Bs[32 * 129];
    int z = blockIdx.z;
    int tid = threadIdx.x;
    int abase = blockIdx.y * 32;
    int tbase = blockIdx.x * 32;
    const float* Ag = z ? Wv : Wq;
    int tx = tid & 31, ty = tid >> 5;
    float acc[4] = {0.f, 0.f, 0.f, 0.f};

    for (int kt = 0; kt < 256; kt += 128) {
        #pragma unroll
        for (int i = 0; i < 16; i++) {
            int f = tid + i * 256;
            int r = f >> 7, c = f & 127;
            As[r * 129 + c] = Ag[(abase + r) * 256 + kt + c];
            Bs[r * 129 + c] = z ? W1[(tbase + r) * 512 + kt + c]
                                : Wk[(tbase + r) * 256 + kt + c];
        }
        __syncthreads();
        #pragma unroll 4
        for (int k = 0; k < 128; k++) {
            float av = As[tx * 129 + k];
            #pragma unroll
            for (int j = 0; j < 4; j++) acc[j] += av * Bs[(ty + 8 * j) * 129 + k];
        }
        __syncthreads();
    }
    int a = abase + tx;
    #pragma unroll
    for (int j = 0; j < 4; j++) {
        int t = tbase + ty + 8 * j;
        __nv_bfloat16 h = __float2bfloat16(acc[j]);
        __nv_bfloat16 l = __float2bfloat16(acc[j] - __bfloat162float(h));
        if (z == 0) { g_Mth [t * 256 + a] = h; g_Mtl [t * 256 + a] = l; }
        else        { g_C1th[t * 256 + a] = h; g_C1tl[t * 256 + a] = l; }
    }
}

// Bt (n-major, bf16 hi/lo): g_Bth[j*256+k] = W1[j*512+256+k]
__global__ void k_prepBt(const float* __restrict__ W1) {
    int j = blockIdx.x, k = threadIdx.x;
    float v = W1[j * 512 + 256 + k];
    __nv_bfloat16 h = __float2bfloat16(v);
    g_Bth[j * 256 + k] = h;
    g_Btl[j * 256 + k] = __float2bfloat16(v - __bfloat162float(h));
}

// ---------------- softmax: segment max, exp, 1-pass gather -----------------------
__global__ void k_smax(const int* __restrict__ ids, int n) {
    int i = blockIdx.x * 256 + threadIdx.x;
    if (i < n) atomicMax(&g_smax[ids[i]], fenc(g_sim[i]));
}
__global__ void k_exp(const int* __restrict__ ids, int n) {
    int i = blockIdx.x * 256 + threadIdx.x;
    if (i < n) g_sim[i] = expf(g_sim[i] - fdec(g_smax[ids[i]]));
}
// block = 256 threads = 4 uids x 64 lanes; single pass over CSR rows
__global__ void k_gather(const float* __restrict__ ue) {
    int u    = blockIdx.x * 4 + (threadIdx.x >> 6);
    int lane = threadIdx.x & 63;
    if (u >= UU) return;
    int s = g_off[u], e = g_off[u + 1];

    float den = 0.0f;
    float4 acc = make_float4(0.f, 0.f, 0.f, 0.f);
    for (int r = s; r < e; r++) {
        int row = g_list[r];
        float ev = g_sim[row];                 // precomputed exp
        den += ev;
        float4 v = *(const float4*)&ue[(size_t)row * 256 + lane * 4];
        acc.x += ev * v.x; acc.y += ev * v.y; acc.z += ev * v.z; acc.w += ev * v.w;
    }
    float inv = (e > s) ? (1.0f / den) : 0.0f;
    acc.x *= inv; acc.y *= inv; acc.z *= inv; acc.w *= inv;
    *(float4*)&g_wsn[(size_t)u * 256 + lane * 4] = acc;
}

// ---------------- tensor-core GEMM (split-bf16, BM=64 BN=128, 4 CTA/SM) ----------
// A is fp32 (ue or g_wsn); loader converts to bf16 hi/lo in-register (no cvt pass).
// grid = (2, rowBlocks): blockIdx.x = 128-col half (co-resident halves share A in L2)
// MODE 0: g_sim[row] += partial rowsum((A @ M) .* sess)               (A = ue)
// MODE 1: g_D = wsn @ Bt + b1                                          (A = g_wsn, extra = b1)
// MODE 2: out = relu(A @ C1 + g_D[ids])                                (A = ue)
template<int MODE>
__global__ __launch_bounds__(128, 4)
void k_mma(const float* __restrict__ Afp, const float* __restrict__ extra,
           const int* __restrict__ ids, float* __restrict__ outp, int nrows) {
    extern __shared__ __align__(16) char smem[];
    uint32_t sbase = (uint32_t)__cvta_generic_to_shared(smem);
    const int tid  = threadIdx.x;
    const int lane = tid & 31;
    const int wid  = tid >> 5;                 // 0..3
    const int mw = wid >> 1, nw = wid & 1;     // 2 x 2 warp grid, warp tile 32x64
    const int blockRow = blockIdx.y * BM;
    const int colBase  = blockIdx.x * BN;

    const float* Ap = (MODE == 1) ? g_wsn : Afp;
    const __nv_bfloat16* Bth = (MODE == 0) ? g_Mth : ((MODE == 1) ? g_Bth : g_C1th);
    const __nv_bfloat16* Btl = (MODE == 0) ? g_Mtl : ((MODE == 1) ? g_Btl : g_C1tl);

    float acc[2][8][4];
    #pragma unroll
    for (int t = 0; t < 2; t++)
        #pragma unroll
        for (int j = 0; j < 8; j++)
            #pragma unroll
            for (int c = 0; c < 4; c++) acc[t][j][c] = 0.0f;

    // ---- A staging: 2 (row, chunk) positions x 8 fp32 ----
    float4 ra[2][2];
    const int r0 = tid >> 2,        ch0 = tid & 3;          // position 0
    const int r1 = (tid + 128) >> 2, ch1 = tid & 3;         // position 1 (tid+128: same ch)
    const bool v0 = true;   // rows 0..31 within 64-row tile always need bounds vs nrows
    auto ldgA = [&](int kt) {
        int g0 = blockRow + r0;
        bool a0 = g0 < nrows;
        const float4* s0 = (const float4*)(Ap + (size_t)(a0 ? g0 : 0) * HH + kt * BK + ch0 * 8);
        ra[0][0] = a0 ? s0[0] : make_float4(0.f, 0.f, 0.f, 0.f);
        ra[0][1] = a0 ? s0[1] : make_float4(0.f, 0.f, 0.f, 0.f);
        int g1 = blockRow + r1;
        bool a1 = g1 < nrows;
        const float4* s1 = (const float4*)(Ap + (size_t)(a1 ? g1 : 0) * HH + kt * BK + ch1 * 8);
        ra[1][0] = a1 ? s1[0] : make_float4(0.f, 0.f, 0.f, 0.f);
        ra[1][1] = a1 ? s1[1] : make_float4(0.f, 0.f, 0.f, 0.f);
    };
    auto stsA = [&](int s) {
        char* db = smem + s * STAGE_BYTES;
        #pragma unroll
        for (int l = 0; l < 2; l++) {
            int r = l ? r1 : r0;
            uint32_t dst = swz(r, ch0);
            uint32_t h0, h1, h2, h3, l0, l1, l2, l3;
            split2(ra[l][0].x, ra[l][0].y, h0, l0);
            split2(ra[l][0].z, ra[l][0].w, h1, l1);
            split2(ra[l][1].x, ra[l][1].y, h2, l2);
            split2(ra[l][1].z, ra[l][1].w, h3, l3);
            *(uint4*)(db + AH_OFF + dst) = make_uint4(h0, h1, h2, h3);
            *(uint4*)(db + AL_OFF + dst) = make_uint4(l0, l1, l2, l3);
        }
    };
    // ---- B loader via cp.async (8 cpa16/thread) ----
    auto cpB = [&](int kt, int s) {
        uint32_t db = sbase + (uint32_t)s * STAGE_BYTES;
        #pragma unroll
        for (int l = 0; l < 4; l++) {
            int u = tid + l * 128;
            int r = u >> 2, ch = u & 3;
            size_t gb = (size_t)(colBase + r) * HH + kt * BK + ch * 8;
            uint32_t dst = swz(r, ch);
            cpa16(db + BH_OFF + dst, Bth + gb, true);
            cpa16(db + BL_OFF + dst, Btl + gb, true);
        }
        asm volatile("cp.async.commit_group;" ::: "memory");
    };

    // ---- prologue ----
    ldgA(0); stsA(0);                 // one exposed LDG latency per CTA
    cpB(0, 0);
    ldgA(1);
    cpB(1, 1);

    const int NKT = HH / BK;   // 8
    for (int kt = 0; kt < NKT; kt++) {
        if (kt < NKT - 1) asm volatile("cp.async.wait_group 1;" ::: "memory");
        else              asm volatile("cp.async.wait_group 0;" ::: "memory");
        if (kt + 1 < NKT) stsA((kt + 1) & 1);     // A(kt+1) from regs (loaded last iter)
        __syncthreads();                          // stage kt fully visible
        if (kt + 2 < NKT) ldgA(kt + 2);           // hide DRAM latency under compute

        uint32_t sb = sbase + (uint32_t)(kt & 1) * STAGE_BYTES;
        #pragma unroll
        for (int k16 = 0; k16 < BK; k16 += 16) {
            uint32_t ah[2][4], al[2][4];
            #pragma unroll
            for (int t = 0; t < 2; t++) {
                int arow = mw * 32 + t * 16 + (lane & 15);
                int cb = (k16 >> 3) + (lane >> 4);
                uint32_t ao = swz(arow, cb);
                ldsm4(ah[t], sb + AH_OFF + ao);
                ldsm4(al[t], sb + AL_OFF + ao);
            }
            #pragma unroll
            for (int p = 0; p < 4; p++) {
                int brow = nw * 64 + p * 16 + (lane & 7) + ((lane >> 4) << 3);
                int cb = (k16 >> 3) + ((lane >> 3) & 1);
                uint32_t bo = swz(brow, cb);
                uint32_t bh[4], bl[4];
                ldsm4(bh, sb + BH_OFF + bo);
                ldsm4(bl, sb + BL_OFF + bo);
                #pragma unroll
                for (int t = 0; t < 2; t++)
                    #pragma unroll
                    for (int q = 0; q < 2; q++)
                        mma16816(acc[t][p * 2 + q], ah[t], &bh[2 * q]);
                #pragma unroll
                for (int t = 0; t < 2; t++)
                    #pragma unroll
                    for (int q = 0; q < 2; q++)
                        mma16816(acc[t][p * 2 + q], ah[t], &bl[2 * q]);
                #pragma unroll
                for (int t = 0; t < 2; t++)
                    #pragma unroll
                    for (int q = 0; q < 2; q++)
                        mma16816(acc[t][p * 2 + q], al[t], &bh[2 * q]);
            }
        }
        __syncthreads();                                    // stage fully consumed
        if (kt + 2 < NKT) cpB(kt + 2, kt & 1);              // refill same stage (B)
    }

    const int lr = lane >> 2;           // 0..7
    const int lc = (lane & 3) * 2;      // 0,2,4,6

    if (MODE == 0) {
        float part[2][2] = {{0.f, 0.f}, {0.f, 0.f}};
        #pragma unroll
        for (int t = 0; t < 2; t++) {
            int row0 = blockRow + mw * 32 + t * 16 + lr;
            #pragma unroll
            for (int j = 0; j < 8; j++) {
                int col = colBase + nw * 64 + j * 8 + lc;
                if (row0 < nrows) {
                    float2 s = *(const float2*)&extra[(size_t)row0 * 256 + col];
                    part[t][0] += acc[t][j][0] * s.x + acc[t][j][1] * s.y;
                }
                if (row0 + 8 < nrows) {
                    float2 s = *(const float2*)&extra[(size_t)(row0 + 8) * 256 + col];
                    part[t][1] += acc[t][j][2] * s.x + acc[t][j][3] * s.y;
                }
            }
        }
        #pragma unroll
        for (int t = 0; t < 2; t++)
            #pragma unroll
            for (int h = 0; h < 2; h++) {
                part[t][h] += __shfl_xor_sync(0xffffffffu, part[t][h], 1);
                part[t][h] += __shfl_xor_sync(0xffffffffu, part[t][h], 2);
            }
        __syncthreads();                 // stage reads done before smem reuse
        float* red = (float*)smem;       // [64][2]
        if ((lane & 3) == 0) {
            #pragma unroll
            for (int t = 0; t < 2; t++) {
                red[(mw * 32 + t * 16 + lr) * 2 + nw]     = part[t][0];
                red[(mw * 32 + t * 16 + lr + 8) * 2 + nw] = part[t][1];
            }
        }
        __syncthreads();
        if (tid < 64) {
            int row = blockRow + tid;
            if (row < nrows) {
                float s = red[tid * 2] + red[tid * 2 + 1];
                asm volatile("red.global.add.f32 [%0], %1;"
                             :: "l"(g_sim + row), "f"(s) : "memory");
            }
        }
    } else if (MODE == 1) {
        #pragma unroll
        for (int t = 0; t < 2; t++)
            #pragma unroll
            for (int h = 0; h < 2; h++) {
                int row = blockRow + mw * 32 + t * 16 + lr + h * 8;
                if (row >= nrows) continue;
                #pragma unroll
                for (int j = 0; j < 8; j++) {
                    int col = colBase + nw * 64 + j * 8 + lc;
                    float2 b = *(const float2*)&extra[col];
                    float2 o;
                    o.x = acc[t][j][2 * h + 0] + b.x;
                    o.y = acc[t][j][2 * h + 1] + b.y;
                    *(float2*)&g_D[(size_t)row * 256 + col] = o;
                }
            }
    } else {
        #pragma unroll
        for (int t = 0; t < 2; t++)
            #pragma unroll
            for (int h = 0; h < 2; h++) {
                int row = blockRow + mw * 32 + t * 16 + lr + h * 8;
                if (row >= nrows) continue;
                int uid = ids[row];
                const float* Dr = g_D + (size_t)uid * 256;
                #pragma unroll
                for (int j = 0; j < 8; j++) {
                    int col = colBase + nw * 64 + j * 8 + lc;
                    float2 d = *(const float2*)&Dr[col];
                    float2 o;
                    o.x = fmaxf(acc[t][j][2 * h + 0] + d.x, 0.0f);
                    o.y = fmaxf(acc[t][j][2 * h + 1] + d.y, 0.0f);
                    *(float2*)&outp[(size_t)row * 256 + col] = o;
                }
            }
    }
}

// ---------------- launch ----------------------------------------------------------
extern "C" void kernel_launch(void* const* d_in, const int* in_sizes, int n_in,
                              void* d_out, int out_size) {
    const float* sess = (const float*)d_in[0];
    const float* ue   = (const float*)d_in[1];
    const int*   ids  = (const int*)d_in[2];   // JAX x64 disabled: int32
    const float* Wq   = (const float*)d_in[3];
    const float* Wk   = (const float*)d_in[4];
    const float* Wv   = (const float*)d_in[5];
    const float* W1   = (const float*)d_in[6];
    const float* b1   = (const float*)d_in[7];
    float*       out  = (float*)d_out;
    int N = in_sizes[0] / HH;   // 200000

    static bool attr_set = false;
    if (!attr_set) {
        cudaFuncSetAttribute(k_mma<0>, cudaFuncAttributeMaxDynamicSharedMemorySize, NSTAGE * STAGE_BYTES);
        cudaFuncSetAttribute(k_mma<1>, cudaFuncAttributeMaxDynamicSharedMemorySize, NSTAGE * STAGE_BYTES);
        cudaFuncSetAttribute(k_mma<2>, cudaFuncAttributeMaxDynamicSharedMemorySize, NSTAGE * STAGE_BYTES);
        attr_set = true;
    }

    dim3 gBig(2, (N + BM - 1) / BM);
    dim3 gU(2, (UU + BM - 1) / BM);
    k_zero<<<(NN + 255) / 256, 256>>>();
    k_prepT<<<dim3(8, 8, 2), 256>>>(Wq, Wk, Wv, W1);
    k_prepBt<<<256, 256>>>(W1);
    k_hist<<<(N + 255) / 256, 256>>>(ids, N);
    k_scan<<<1, 256>>>();
    k_fill<<<(N + 255) / 256, 256>>>(ids, N);
    k_mma<0><<<gBig, 128, NSTAGE * STAGE_BYTES>>>(ue, sess, ids, nullptr, N);
    k_smax<<<(N + 255) / 256, 256>>>(ids, N);
    k_exp<<<(N + 255) / 256, 256>>>(ids, N);
    k_gather<<<(UU + 3) / 4, 256>>>(ue);
    k_mma<1><<<gU, 128, NSTAGE * STAGE_BYTES>>>(nullptr, b1, nullptr, nullptr, UU);
    k_mma<2><<<gBig, 128, NSTAGE * STAGE_BYTES>>>(ue, nullptr, ids, out, N);
}

// round 14
// speedup vs baseline: 2.8990x; 1.1080x over previous
#include <cuda_runtime.h>
#include <cuda_bf16.h>
#include <cstdint>

#define NN 200000
#define UU 20000
#define HH 256

#define BM 64
#define BN 128
#define BK 32
#define AH_OFF 0
#define AL_OFF 4096
#define BH_OFF 8192
#define BL_OFF 16384
#define STAGE_BYTES 24576
#define NSTAGE 2
// tf32 kernel stage: A 64x32 fp32 (8KB) + B 128x32 fp32 (16KB)
#define TF_A_OFF 0
#define TF_B_OFF 8192
#define TF_STAGE 24576

// ---------------- scratch (device globals) -------------------------------------
__device__ __align__(16) __nv_bfloat16 g_Mth [HH * HH], g_Mtl [HH * HH];  // M^T  hi/lo (n-major)
__device__ __align__(16) float         g_C1f [HH * HH];                    // C1^T tf32-rounded fp32 (n-major)
__device__ __align__(16) __nv_bfloat16 g_Bth [HH * HH], g_Btl [HH * HH];  // W1[:,H:]  (n-major) hi/lo
__device__ __align__(16) float    g_wsn[UU * HH];   // normalized weighted sum (fp32)
__device__ __align__(16) float    g_D  [UU * HH];
__device__ __align__(16) float    g_sim[NN];
__device__ __align__(16) unsigned g_smax[UU];
__device__ int g_list[NN];          // CSR row lists
__device__ int g_off [UU + 1];
__device__ int g_cnt [UU];
__device__ int g_cnt2[UU];

// ---------------- helpers -------------------------------------------------------
__device__ __forceinline__ unsigned fenc(float f) {
    unsigned u = __float_as_uint(f);
    return (u & 0x80000000u) ? ~u : (u | 0x80000000u);
}
__device__ __forceinline__ float fdec(unsigned u) {
    return (u & 0x80000000u) ? __uint_as_float(u & 0x7FFFFFFFu) : __uint_as_float(~u);
}
__device__ __forceinline__ void ldsm4(uint32_t* r, uint32_t addr) {
    asm volatile("ldmatrix.sync.aligned.m8n8.x4.shared.b16 {%0,%1,%2,%3}, [%4];"
                 : "=r"(r[0]), "=r"(r[1]), "=r"(r[2]), "=r"(r[3]) : "r"(addr));
}
__device__ __forceinline__ void mma16816(float* c, const uint32_t* a, const uint32_t* b) {
    asm volatile("mma.sync.aligned.m16n8k16.row.col.f32.bf16.bf16.f32 "
                 "{%0,%1,%2,%3}, {%4,%5,%6,%7}, {%8,%9}, {%0,%1,%2,%3};"
                 : "+f"(c[0]), "+f"(c[1]), "+f"(c[2]), "+f"(c[3])
                 : "r"(a[0]), "r"(a[1]), "r"(a[2]), "r"(a[3]), "r"(b[0]), "r"(b[1]));
}
__device__ __forceinline__ void mma_tf(float* c, const uint32_t* a, const uint32_t* b) {
    asm volatile("mma.sync.aligned.m16n8k8.row.col.f32.tf32.tf32.f32 "
                 "{%0,%1,%2,%3}, {%4,%5,%6,%7}, {%8,%9}, {%0,%1,%2,%3};"
                 : "+f"(c[0]), "+f"(c[1]), "+f"(c[2]), "+f"(c[3])
                 : "r"(a[0]), "r"(a[1]), "r"(a[2]), "r"(a[3]), "r"(b[0]), "r"(b[1]));
}
__device__ __forceinline__ void cpa16(uint32_t dst, const void* src, bool v) {
    int sz = v ? 16 : 0;
    asm volatile("cp.async.cg.shared.global [%0], [%1], 16, %2;"
                 :: "r"(dst), "l"(src), "r"(sz));
}
// swizzled byte offset of (row, 16B-chunk ch) in a 64B-stride tile
__device__ __forceinline__ uint32_t swz(int row, int ch) {
    return (uint32_t)(row * 64 + ((ch ^ ((row >> 1) & 3)) * 16));
}
// swizzled byte offset of (row, 16B-chunk ch) in a 128B-stride tile
__device__ __forceinline__ uint32_t swz128(int row, int ch) {
    return (uint32_t)(row * 128 + ((ch ^ (row & 7)) * 16));
}
// 2 fp32 -> packed bf16x2 hi and lo digits
__device__ __forceinline__ void split2(float x, float y, uint32_t& hi, uint32_t& lo) {
    __nv_bfloat16 h0 = __float2bfloat16(x), h1 = __float2bfloat16(y);
    __nv_bfloat162 hp = __halves2bfloat162(h0, h1);
    hi = *(uint32_t*)&hp;
    __nv_bfloat16 l0 = __float2bfloat16(x - __bfloat162float(h0));
    __nv_bfloat16 l1 = __float2bfloat16(y - __bfloat162float(h1));
    __nv_bfloat162 lp = __halves2bfloat162(l0, l1);
    lo = *(uint32_t*)&lp;
}
// fp32 bits -> tf32-rounded bits (round to nearest)
__device__ __forceinline__ uint32_t rna(uint32_t x) {
    uint32_t y;
    asm("cvt.rna.tf32.f32 %0, %1;" : "=r"(y) : "f"(__uint_as_float(x)));
    return y;
}

// ---------------- init scratch -------------------------------------------------
__global__ void k_zero() {
    int idx = blockIdx.x * 256 + threadIdx.x;
    if (idx < NN) g_sim[idx] = 0.0f;
    if (idx < UU) { g_cnt[idx] = 0; g_cnt2[idx] = 0; g_smax[idx] = 0u; }
}

// ---------------- CSR build: hist -> scan -> fill --------------------------------
__global__ void k_hist(const int* __restrict__ ids, int n) {
    int i = blockIdx.x * 256 + threadIdx.x;
    if (i < n) atomicAdd(&g_cnt[ids[i]], 1);
}
__global__ void k_scan() {             // single block, 256 threads
    __shared__ int ps[256];
    const int C = (UU + 255) / 256;    // 79
    int t = threadIdx.x;
    int s = 0;
    for (int j = 0; j < C; j++) { int i = t * C + j; if (i < UU) s += g_cnt[i]; }
    ps[t] = s;
    __syncthreads();
    int acc = 0;
    for (int j = 0; j < t; j++) acc += ps[j];
    int run = acc;
    for (int j = 0; j < C; j++) {
        int i = t * C + j;
        if (i < UU) { g_off[i] = run; run += g_cnt[i]; }
    }
    if (t == 255) g_off[UU] = run;
}
__global__ void k_fill(const int* __restrict__ ids, int n) {
    int i = blockIdx.x * 256 + threadIdx.x;
    if (i < n) {
        int uid = ids[i];
        int pos = g_off[uid] + atomicAdd(&g_cnt2[uid], 1);
        g_list[pos] = i;
    }
}

// ---------------- coalesced precompute GEMMs -----------------------------------
// z==0: M[a,t]  = Wq[a,:]·Wk[t,:]      -> g_Mth/l [t*256+a] (bf16 hi/lo)
// z==1: C1[a,t] = Wv[a,:]·W1[t,0:256]  -> g_C1f  [t*256+a] (tf32-rounded fp32)
__global__ void k_prepT(const float* __restrict__ Wq, const float* __restrict__ Wk,
                        const float* __restrict__ Wv, const float* __restrict__ W1) {
    __shared__ float As[32 * 129];
    __shared__ float Bs[32 * 129];
    int z = blockIdx.z;
    int tid = threadIdx.x;
    int abase = blockIdx.y * 32;
    int tbase = blockIdx.x * 32;
    const float* Ag = z ? Wv : Wq;
    int tx = tid & 31, ty = tid >> 5;
    float acc[4] = {0.f, 0.f, 0.f, 0.f};

    for (int kt = 0; kt < 256; kt += 128) {
        #pragma unroll
        for (int i = 0; i < 16; i++) {
            int f = tid + i * 256;
            int r = f >> 7, c = f & 127;
            As[r * 129 + c] = Ag[(abase + r) * 256 + kt + c];
            Bs[r * 129 + c] = z ? W1[(tbase + r) * 512 + kt + c]
                                : Wk[(tbase + r) * 256 + kt + c];
        }
        __syncthreads();
        #pragma unroll 4
        for (int k = 0; k < 128; k++) {
            float av = As[tx * 129 + k];
            #pragma unroll
            for (int j = 0; j < 4; j++) acc[j] += av * Bs[(ty + 8 * j) * 129 + k];
        }
        __syncthreads();
    }
    int a = abase + tx;
    #pragma unroll
    for (int j = 0; j < 4; j++) {
        int t = tbase + ty + 8 * j;
        if (z == 0) {
            __nv_bfloat16 h = __float2bfloat16(acc[j]);
            __nv_bfloat16 l = __float2bfloat16(acc[j] - __bfloat162float(h));
            g_Mth[t * 256 + a] = h;
            g_Mtl[t * 256 + a] = l;
        } else {
            g_C1f[t * 256 + a] = __uint_as_float(rna(__float_as_uint(acc[j])));
        }
    }
}

// Bt (n-major, bf16 hi/lo): g_Bth[j*256+k] = W1[j*512+256+k]
__global__ void k_prepBt(const float* __restrict__ W1) {
    int j = blockIdx.x, k = threadIdx.x;
    float v = W1[j * 512 + 256 + k];
    __nv_bfloat16 h = __float2bfloat16(v);
    g_Bth[j * 256 + k] = h;
    g_Btl[j * 256 + k] = __float2bfloat16(v - __bfloat162float(h));
}

// ---------------- softmax: segment max, exp, 1-pass gather -----------------------
__global__ void k_smax(const int* __restrict__ ids, int n) {
    int i = blockIdx.x * 256 + threadIdx.x;
    if (i < n) atomicMax(&g_smax[ids[i]], fenc(g_sim[i]));
}
__global__ void k_exp(const int* __restrict__ ids, int n) {
    int i = blockIdx.x * 256 + threadIdx.x;
    if (i < n) g_sim[i] = expf(g_sim[i] - fdec(g_smax[ids[i]]));
}
__global__ void k_gather(const float* __restrict__ ue) {
    int u    = blockIdx.x * 4 + (threadIdx.x >> 6);
    int lane = threadIdx.x & 63;
    if (u >= UU) return;
    int s = g_off[u], e = g_off[u + 1];

    float den = 0.0f;
    float4 acc = make_float4(0.f, 0.f, 0.f, 0.f);
    for (int r = s; r < e; r++) {
        int row = g_list[r];
        float ev = g_sim[row];                 // precomputed exp
        den += ev;
        float4 v = *(const float4*)&ue[(size_t)row * 256 + lane * 4];
        acc.x += ev * v.x; acc.y += ev * v.y; acc.z += ev * v.z; acc.w += ev * v.w;
    }
    float inv = (e > s) ? (1.0f / den) : 0.0f;
    acc.x *= inv; acc.y *= inv; acc.z *= inv; acc.w *= inv;
    *(float4*)&g_wsn[(size_t)u * 256 + lane * 4] = acc;
}

// ---------------- bf16 split GEMM (MODE 0/1), BM=64 BN=128, 4 CTA/SM -------------
// A fp32 (ue or g_wsn), converted to bf16 hi/lo in-register.
// MODE 0: g_sim[row] += partial rowsum((A @ M) .* sess)
// MODE 1: g_D = wsn @ Bt + b1
template<int MODE>
__global__ __launch_bounds__(128, 4)
void k_mma(const float* __restrict__ Afp, const float* __restrict__ extra,
           const int* __restrict__ ids, float* __restrict__ outp, int nrows) {
    extern __shared__ __align__(16) char smem[];
    uint32_t sbase = (uint32_t)__cvta_generic_to_shared(smem);
    const int tid  = threadIdx.x;
    const int lane = tid & 31;
    const int wid  = tid >> 5;
    const int mw = wid >> 1, nw = wid & 1;
    const int blockRow = blockIdx.y * BM;
    const int colBase  = blockIdx.x * BN;

    const float* Ap = (MODE == 1) ? g_wsn : Afp;
    const __nv_bfloat16* Bth = (MODE == 0) ? g_Mth : g_Bth;
    const __nv_bfloat16* Btl = (MODE == 0) ? g_Mtl : g_Btl;

    float acc[2][8][4];
    #pragma unroll
    for (int t = 0; t < 2; t++)
        #pragma unroll
        for (int j = 0; j < 8; j++)
            #pragma unroll
            for (int c = 0; c < 4; c++) acc[t][j][c] = 0.0f;

    float4 ra[2][2];
    const int r0 = tid >> 2,         ch0 = tid & 3;
    const int r1 = (tid + 128) >> 2;
    auto ldgA = [&](int kt) {
        int g0 = blockRow + r0;
        bool a0 = g0 < nrows;
        const float4* s0 = (const float4*)(Ap + (size_t)(a0 ? g0 : 0) * HH + kt * BK + ch0 * 8);
        ra[0][0] = a0 ? s0[0] : make_float4(0.f, 0.f, 0.f, 0.f);
        ra[0][1] = a0 ? s0[1] : make_float4(0.f, 0.f, 0.f, 0.f);
        int g1 = blockRow + r1;
        bool a1 = g1 < nrows;
        const float4* s1 = (const float4*)(Ap + (size_t)(a1 ? g1 : 0) * HH + kt * BK + ch0 * 8);
        ra[1][0] = a1 ? s1[0] : make_float4(0.f, 0.f, 0.f, 0.f);
        ra[1][1] = a1 ? s1[1] : make_float4(0.f, 0.f, 0.f, 0.f);
    };
    auto stsA = [&](int s) {
        char* db = smem + s * STAGE_BYTES;
        #pragma unroll
        for (int l = 0; l < 2; l++) {
            int r = l ? r1 : r0;
            uint32_t dst = swz(r, ch0);
            uint32_t h0, h1, h2, h3, l0, l1, l2, l3;
            split2(ra[l][0].x, ra[l][0].y, h0, l0);
            split2(ra[l][0].z, ra[l][0].w, h1, l1);
            split2(ra[l][1].x, ra[l][1].y, h2, l2);
            split2(ra[l][1].z, ra[l][1].w, h3, l3);
            *(uint4*)(db + AH_OFF + dst) = make_uint4(h0, h1, h2, h3);
            *(uint4*)(db + AL_OFF + dst) = make_uint4(l0, l1, l2, l3);
        }
    };
    auto cpB = [&](int kt, int s) {
        uint32_t db = sbase + (uint32_t)s * STAGE_BYTES;
        #pragma unroll
        for (int l = 0; l < 4; l++) {
            int u = tid + l * 128;
            int r = u >> 2, ch = u & 3;
            size_t gb = (size_t)(colBase + r) * HH + kt * BK + ch * 8;
            uint32_t dst = swz(r, ch);
            cpa16(db + BH_OFF + dst, Bth + gb, true);
            cpa16(db + BL_OFF + dst, Btl + gb, true);
        }
        asm volatile("cp.async.commit_group;" ::: "memory");
    };

    ldgA(0); stsA(0);
    cpB(0, 0);
    ldgA(1);
    cpB(1, 1);

    const int NKT = HH / BK;   // 8
    for (int kt = 0; kt < NKT; kt++) {
        if (kt < NKT - 1) asm volatile("cp.async.wait_group 1;" ::: "memory");
        else              asm volatile("cp.async.wait_group 0;" ::: "memory");
        if (kt + 1 < NKT) stsA((kt + 1) & 1);
        __syncthreads();
        if (kt + 2 < NKT) ldgA(kt + 2);

        uint32_t sb = sbase + (uint32_t)(kt & 1) * STAGE_BYTES;
        #pragma unroll
        for (int k16 = 0; k16 < BK; k16 += 16) {
            uint32_t ah[2][4], al[2][4];
            #pragma unroll
            for (int t = 0; t < 2; t++) {
                int arow = mw * 32 + t * 16 + (lane & 15);
                int cb = (k16 >> 3) + (lane >> 4);
                uint32_t ao = swz(arow, cb);
                ldsm4(ah[t], sb + AH_OFF + ao);
                ldsm4(al[t], sb + AL_OFF + ao);
            }
            #pragma unroll
            for (int p = 0; p < 4; p++) {
                int brow = nw * 64 + p * 16 + (lane & 7) + ((lane >> 4) << 3);
                int cb = (k16 >> 3) + ((lane >> 3) & 1);
                uint32_t bo = swz(brow, cb);
                uint32_t bh[4], bl[4];
                ldsm4(bh, sb + BH_OFF + bo);
                ldsm4(bl, sb + BL_OFF + bo);
                #pragma unroll
                for (int t = 0; t < 2; t++)
                    #pragma unroll
                    for (int q = 0; q < 2; q++)
                        mma16816(acc[t][p * 2 + q], ah[t], &bh[2 * q]);
                #pragma unroll
                for (int t = 0; t < 2; t++)
                    #pragma unroll
                    for (int q = 0; q < 2; q++)
                        mma16816(acc[t][p * 2 + q], ah[t], &bl[2 * q]);
                #pragma unroll
                for (int t = 0; t < 2; t++)
                    #pragma unroll
                    for (int q = 0; q < 2; q++)
                        mma16816(acc[t][p * 2 + q], al[t], &bh[2 * q]);
            }
        }
        __syncthreads();
        if (kt + 2 < NKT) cpB(kt + 2, kt & 1);
    }

    const int lr = lane >> 2;
    const int lc = (lane & 3) * 2;

    if (MODE == 0) {
        float part[2][2] = {{0.f, 0.f}, {0.f, 0.f}};
        #pragma unroll
        for (int t = 0; t < 2; t++) {
            int row0 = blockRow + mw * 32 + t * 16 + lr;
            #pragma unroll
            for (int j = 0; j < 8; j++) {
                int col = colBase + nw * 64 + j * 8 + lc;
                if (row0 < nrows) {
                    float2 s = *(const float2*)&extra[(size_t)row0 * 256 + col];
                    part[t][0] += acc[t][j][0] * s.x + acc[t][j][1] * s.y;
                }
                if (row0 + 8 < nrows) {
                    float2 s = *(const float2*)&extra[(size_t)(row0 + 8) * 256 + col];
                    part[t][1] += acc[t][j][2] * s.x + acc[t][j][3] * s.y;
                }
            }
        }
        #pragma unroll
        for (int t = 0; t < 2; t++)
            #pragma unroll
            for (int h = 0; h < 2; h++) {
                part[t][h] += __shfl_xor_sync(0xffffffffu, part[t][h], 1);
                part[t][h] += __shfl_xor_sync(0xffffffffu, part[t][h], 2);
            }
        __syncthreads();
        float* red = (float*)smem;
        if ((lane & 3) == 0) {
            #pragma unroll
            for (int t = 0; t < 2; t++) {
                red[(mw * 32 + t * 16 + lr) * 2 + nw]     = part[t][0];
                red[(mw * 32 + t * 16 + lr + 8) * 2 + nw] = part[t][1];
            }
        }
        __syncthreads();
        if (tid < 64) {
            int row = blockRow + tid;
            if (row < nrows) {
                float s = red[tid * 2] + red[tid * 2 + 1];
                asm volatile("red.global.add.f32 [%0], %1;"
                             :: "l"(g_sim + row), "f"(s) : "memory");
            }
        }
    } else {
        #pragma unroll
        for (int t = 0; t < 2; t++)
            #pragma unroll
            for (int h = 0; h < 2; h++) {
                int row = blockRow + mw * 32 + t * 16 + lr + h * 8;
                if (row >= nrows) continue;
                #pragma unroll
                for (int j = 0; j < 8; j++) {
                    int col = colBase + nw * 64 + j * 8 + lc;
                    float2 b = *(const float2*)&extra[col];
                    float2 o;
                    o.x = acc[t][j][2 * h + 0] + b.x;
                    o.y = acc[t][j][2 * h + 1] + b.y;
                    *(float2*)&g_D[(size_t)row * 256 + col] = o;
                }
            }
    }
}

// ---------------- tf32 GEMM (MODE 2): out = relu(ue @ C1 + g_D[ids]) -------------
// A = ue fp32 (rna-rounded in-register), B = g_C1f (pre-rounded). 1 MMA per k8.
__global__ __launch_bounds__(128, 4)
void k_tf(const float* __restrict__ Afp, const int* __restrict__ ids,
          float* __restrict__ outp, int nrows) {
    extern __shared__ __align__(16) char smem[];
    uint32_t sbase = (uint32_t)__cvta_generic_to_shared(smem);
    const int tid  = threadIdx.x;
    const int lane = tid & 31;
    const int wid  = tid >> 5;
    const int mw = wid >> 1, nw = wid & 1;     // warp tile 32 x 64
    const int blockRow = blockIdx.y * BM;
    const int colBase  = blockIdx.x * BN;

    float acc[2][8][4];
    #pragma unroll
    for (int t = 0; t < 2; t++)
        #pragma unroll
        for (int j = 0; j < 8; j++)
            #pragma unroll
            for (int c = 0; c < 4; c++) acc[t][j][c] = 0.0f;

    // loader: A 64x32 fp32 (4 cpa16/thr) + B 128x32 fp32 (8 cpa16/thr)
    auto load_stage = [&](int kt, int s) {
        uint32_t db = sbase + (uint32_t)s * TF_STAGE;
        #pragma unroll
        for (int l = 0; l < 4; l++) {
            int u = tid + l * 128;
            int r = u >> 3, ch = u & 7;
            int grow = blockRow + r;
            bool v = grow < nrows;
            size_t ga = (size_t)(v ? grow : 0) * HH + kt * BK + ch * 4;
            cpa16(db + TF_A_OFF + swz128(r, ch), Afp + ga, v);
        }
        #pragma unroll
        for (int l = 0; l < 8; l++) {
            int u = tid + l * 128;
            int r = u >> 3, ch = u & 7;
            size_t gb = (size_t)(colBase + r) * HH + kt * BK + ch * 4;
            cpa16(db + TF_B_OFF + swz128(r, ch), g_C1f + gb, true);
        }
        asm volatile("cp.async.commit_group;" ::: "memory");
    };

    load_stage(0, 0);
    load_stage(1, 1);

    const int NKT = HH / BK;   // 8
    for (int kt = 0; kt < NKT; kt++) {
        if (kt < NKT - 1) asm volatile("cp.async.wait_group 1;" ::: "memory");
        else              asm volatile("cp.async.wait_group 0;" ::: "memory");
        __syncthreads();

        uint32_t sb = sbase + (uint32_t)(kt & 1) * TF_STAGE;
        #pragma unroll
        for (int k8 = 0; k8 < 4; k8++) {                       // BK=32 fp32 = 4 k8 steps
            uint32_t av[2][4];
            #pragma unroll
            for (int t = 0; t < 2; t++) {
                int arow = mw * 32 + t * 16 + (lane & 7) + ((lane >> 3) & 1) * 8;
                int ch = k8 * 2 + (lane >> 4);
                ldsm4(av[t], sb + TF_A_OFF + swz128(arow, ch));
                av[t][0] = rna(av[t][0]); av[t][1] = rna(av[t][1]);
                av[t][2] = rna(av[t][2]); av[t][3] = rna(av[t][3]);
            }
            #pragma unroll
            for (int p = 0; p < 4; p++) {
                int brow = nw * 64 + p * 16 + (lane & 7) + ((lane >> 4) << 3);
                int bch = k8 * 2 + ((lane >> 3) & 1);
                uint32_t bv[4];
                ldsm4(bv, sb + TF_B_OFF + swz128(brow, bch));
                #pragma unroll
                for (int t = 0; t < 2; t++)
                    #pragma unroll
                    for (int q = 0; q < 2; q++)
                        mma_tf(acc[t][p * 2 + q], av[t], &bv[2 * q]);
            }
        }
        __syncthreads();
        if (kt + 2 < NKT) load_stage(kt + 2, kt & 1);
    }

    const int lr = lane >> 2;
    const int lc = (lane & 3) * 2;
    #pragma unroll
    for (int t = 0; t < 2; t++)
        #pragma unroll
        for (int h = 0; h < 2; h++) {
            int row = blockRow + mw * 32 + t * 16 + lr + h * 8;
            if (row >= nrows) continue;
            int uid = ids[row];
            const float* Dr = g_D + (size_t)uid * 256;
            #pragma unroll
            for (int j = 0; j < 8; j++) {
                int col = colBase + nw * 64 + j * 8 + lc;
                float2 d = *(const float2*)&Dr[col];
                float2 o;
                o.x = fmaxf(acc[t][j][2 * h + 0] + d.x, 0.0f);
                o.y = fmaxf(acc[t][j][2 * h + 1] + d.y, 0.0f);
                *(float2*)&outp[(size_t)row * 256 + col] = o;
            }
        }
}

// ---------------- launch ----------------------------------------------------------
extern "C" void kernel_launch(void* const* d_in, const int* in_sizes, int n_in,
                              void* d_out, int out_size) {
    const float* sess = (const float*)d_in[0];
    const float* ue   = (const float*)d_in[1];
    const int*   ids  = (const int*)d_in[2];   // JAX x64 disabled: int32
    const float* Wq   = (const float*)d_in[3];
    const float* Wk   = (const float*)d_in[4];
    const float* Wv   = (const float*)d_in[5];
    const float* W1   = (const float*)d_in[6];
    const float* b1   = (const float*)d_in[7];
    float*       out  = (float*)d_out;
    int N = in_sizes[0] / HH;   // 200000

    static bool attr_set = false;
    if (!attr_set) {
        cudaFuncSetAttribute(k_mma<0>, cudaFuncAttributeMaxDynamicSharedMemorySize, NSTAGE * STAGE_BYTES);
        cudaFuncSetAttribute(k_mma<1>, cudaFuncAttributeMaxDynamicSharedMemorySize, NSTAGE * STAGE_BYTES);
        cudaFuncSetAttribute(k_tf,     cudaFuncAttributeMaxDynamicSharedMemorySize, NSTAGE * TF_STAGE);
        attr_set = true;
    }

    dim3 gBig(2, (N + BM - 1) / BM);
    dim3 gU(2, (UU + BM - 1) / BM);
    k_zero<<<(NN + 255) / 256, 256>>>();
    k_prepT<<<dim3(8, 8, 2), 256>>>(Wq, Wk, Wv, W1);
    k_prepBt<<<256, 256>>>(W1);
    k_hist<<<(N + 255) / 256, 256>>>(ids, N);
    k_scan<<<1, 256>>>();
    k_fill<<<(N + 255) / 256, 256>>>(ids, N);
    k_mma<0><<<gBig, 128, NSTAGE * STAGE_BYTES>>>(ue, sess, ids, nullptr, N);
    k_smax<<<(N + 255) / 256, 256>>>(ids, N);
    k_exp<<<(N + 255) / 256, 256>>>(ids, N);
    k_gather<<<(UU + 3) / 4, 256>>>(ue);
    k_mma<1><<<gU, 128, NSTAGE * STAGE_BYTES>>>(nullptr, b1, nullptr, nullptr, UU);
    k_tf<<<gBig, 128, NSTAGE * TF_STAGE>>>(ue, ids, out, N);
}

// round 15
// speedup vs baseline: 2.9255x; 1.0091x over previous
#include <cuda_runtime.h>
#include <cuda_bf16.h>
#include <cstdint>

#define NN 200000
#define UU 20000
#define HH 256

#define BM 64
#define BN 128
#define BK 32
#define AH_OFF 0
#define AL_OFF 4096
#define BH_OFF 8192
#define BL_OFF 16384
#define STAGE_BYTES 24576
#define NSTAGE 2
// tf32 kernel stage: A 64x32 fp32 (8KB) + B 128x32 fp32 (16KB)
#define TF_A_OFF 0
#define TF_B_OFF 8192
#define TF_STAGE 24576

// ---------------- scratch (device globals) -------------------------------------
__device__ __align__(16) __nv_bfloat16 g_Mth [HH * HH], g_Mtl [HH * HH];  // M^T  hi/lo (n-major)
__device__ __align__(16) float         g_C1f [HH * HH];                    // C1^T tf32-rounded fp32 (n-major)
__device__ __align__(16) __nv_bfloat16 g_Bth [HH * HH], g_Btl [HH * HH];  // W1[:,H:]  (n-major) hi/lo
__device__ __align__(16) float    g_wsn[UU * HH];   // normalized weighted sum (fp32)
__device__ __align__(16) float    g_D  [UU * HH];
__device__ __align__(16) float    g_sim[NN];
__device__ __align__(16) unsigned g_smax[UU];
__device__ int g_list[NN];          // CSR row lists
__device__ int g_off [UU + 1];
__device__ int g_cnt [UU];
__device__ int g_cnt2[UU];

// ---------------- helpers -------------------------------------------------------
__device__ __forceinline__ unsigned fenc(float f) {
    unsigned u = __float_as_uint(f);
    return (u & 0x80000000u) ? ~u : (u | 0x80000000u);
}
__device__ __forceinline__ float fdec(unsigned u) {
    return (u & 0x80000000u) ? __uint_as_float(u & 0x7FFFFFFFu) : __uint_as_float(~u);
}
__device__ __forceinline__ void ldsm4(uint32_t* r, uint32_t addr) {
    asm volatile("ldmatrix.sync.aligned.m8n8.x4.shared.b16 {%0,%1,%2,%3}, [%4];"
                 : "=r"(r[0]), "=r"(r[1]), "=r"(r[2]), "=r"(r[3]) : "r"(addr));
}
__device__ __forceinline__ void mma16816(float* c, const uint32_t* a, const uint32_t* b) {
    asm volatile("mma.sync.aligned.m16n8k16.row.col.f32.bf16.bf16.f32 "
                 "{%0,%1,%2,%3}, {%4,%5,%6,%7}, {%8,%9}, {%0,%1,%2,%3};"
                 : "+f"(c[0]), "+f"(c[1]), "+f"(c[2]), "+f"(c[3])
                 : "r"(a[0]), "r"(a[1]), "r"(a[2]), "r"(a[3]), "r"(b[0]), "r"(b[1]));
}
__device__ __forceinline__ void mma_tf(float* c, const uint32_t* a, const uint32_t* b) {
    asm volatile("mma.sync.aligned.m16n8k8.row.col.f32.tf32.tf32.f32 "
                 "{%0,%1,%2,%3}, {%4,%5,%6,%7}, {%8,%9}, {%0,%1,%2,%3};"
                 : "+f"(c[0]), "+f"(c[1]), "+f"(c[2]), "+f"(c[3])
                 : "r"(a[0]), "r"(a[1]), "r"(a[2]), "r"(a[3]), "r"(b[0]), "r"(b[1]));
}
__device__ __forceinline__ void cpa16(uint32_t dst, const void* src, bool v) {
    int sz = v ? 16 : 0;
    asm volatile("cp.async.cg.shared.global [%0], [%1], 16, %2;"
                 :: "r"(dst), "l"(src), "r"(sz));
}
__device__ __forceinline__ uint32_t swz(int row, int ch) {
    return (uint32_t)(row * 64 + ((ch ^ ((row >> 1) & 3)) * 16));
}
__device__ __forceinline__ uint32_t swz128(int row, int ch) {
    return (uint32_t)(row * 128 + ((ch ^ (row & 7)) * 16));
}
__device__ __forceinline__ void split2(float x, float y, uint32_t& hi, uint32_t& lo) {
    __nv_bfloat16 h0 = __float2bfloat16(x), h1 = __float2bfloat16(y);
    __nv_bfloat162 hp = __halves2bfloat162(h0, h1);
    hi = *(uint32_t*)&hp;
    __nv_bfloat16 l0 = __float2bfloat16(x - __bfloat162float(h0));
    __nv_bfloat16 l1 = __float2bfloat16(y - __bfloat162float(h1));
    __nv_bfloat162 lp = __halves2bfloat162(l0, l1);
    lo = *(uint32_t*)&lp;
}
__device__ __forceinline__ uint32_t rna(uint32_t x) {
    uint32_t y;
    asm("cvt.rna.tf32.f32 %0, %1;" : "=r"(y) : "f"(__uint_as_float(x)));
    return y;
}

// ---------------- init scratch -------------------------------------------------
__global__ void k_zero() {
    int idx = blockIdx.x * 256 + threadIdx.x;
    if (idx < NN) g_sim[idx] = 0.0f;
    if (idx < UU) { g_cnt[idx] = 0; g_cnt2[idx] = 0; g_smax[idx] = 0u; }
}

// ---------------- CSR build: hist -> scan -> fill --------------------------------
__global__ void k_hist(const int* __restrict__ ids, int n) {
    int i = blockIdx.x * 256 + threadIdx.x;
    if (i < n) atomicAdd(&g_cnt[ids[i]], 1);
}
__global__ void k_scan() {             // single block, 256 threads
    __shared__ int ps[256];
    const int C = (UU + 255) / 256;    // 79
    int t = threadIdx.x;
    int s = 0;
    for (int j = 0; j < C; j++) { int i = t * C + j; if (i < UU) s += g_cnt[i]; }
    ps[t] = s;
    __syncthreads();
    int acc = 0;
    for (int j = 0; j < t; j++) acc += ps[j];
    int run = acc;
    for (int j = 0; j < C; j++) {
        int i = t * C + j;
        if (i < UU) { g_off[i] = run; run += g_cnt[i]; }
    }
    if (t == 255) g_off[UU] = run;
}
__global__ void k_fill(const int* __restrict__ ids, int n) {
    int i = blockIdx.x * 256 + threadIdx.x;
    if (i < n) {
        int uid = ids[i];
        int pos = g_off[uid] + atomicAdd(&g_cnt2[uid], 1);
        g_list[pos] = i;
    }
}

// ---------------- coalesced precompute GEMMs -----------------------------------
// z==0: M[a,t]  = Wq[a,:]·Wk[t,:]      -> g_Mth/l [t*256+a] (bf16 hi/lo)
// z==1: C1[a,t] = Wv[a,:]·W1[t,0:256]  -> g_C1f  [t*256+a] (tf32-rounded fp32)
__global__ void k_prepT(const float* __restrict__ Wq, const float* __restrict__ Wk,
                        const float* __restrict__ Wv, const float* __restrict__ W1) {
    __shared__ float As[32 * 129];
    __shared__ float Bs[32 * 129];
    int z = blockIdx.z;
    int tid = threadIdx.x;
    int abase = blockIdx.y * 32;
    int tbase = blockIdx.x * 32;
    const float* Ag = z ? Wv : Wq;
    int tx = tid & 31, ty = tid >> 5;
    float acc[4] = {0.f, 0.f, 0.f, 0.f};

    for (int kt = 0; kt < 256; kt += 128) {
        #pragma unroll
        for (int i = 0; i < 16; i++) {
            int f = tid + i * 256;
            int r = f >> 7, c = f & 127;
            As[r * 129 + c] = Ag[(abase + r) * 256 + kt + c];
            Bs[r * 129 + c] = z ? W1[(tbase + r) * 512 + kt + c]
                                : Wk[(tbase + r) * 256 + kt + c];
        }
        __syncthreads();
        #pragma unroll 4
        for (int k = 0; k < 128; k++) {
            float av = As[tx * 129 + k];
            #pragma unroll
            for (int j = 0; j < 4; j++) acc[j] += av * Bs[(ty + 8 * j) * 129 + k];
        }
        __syncthreads();
    }
    int a = abase + tx;
    #pragma unroll
    for (int j = 0; j < 4; j++) {
        int t = tbase + ty + 8 * j;
        if (z == 0) {
            __nv_bfloat16 h = __float2bfloat16(acc[j]);
            __nv_bfloat16 l = __float2bfloat16(acc[j] - __bfloat162float(h));
            g_Mth[t * 256 + a] = h;
            g_Mtl[t * 256 + a] = l;
        } else {
            g_C1f[t * 256 + a] = __uint_as_float(rna(__float_as_uint(acc[j])));
        }
    }
}

// Bt (n-major, bf16 hi/lo): g_Bth[j*256+k] = W1[j*512+256+k]
__global__ void k_prepBt(const float* __restrict__ W1) {
    int j = blockIdx.x, k = threadIdx.x;
    float v = W1[j * 512 + 256 + k];
    __nv_bfloat16 h = __float2bfloat16(v);
    g_Bth[j * 256 + k] = h;
    g_Btl[j * 256 + k] = __float2bfloat16(v - __bfloat162float(h));
}

// ---------------- softmax: segment max, exp, 1-pass gather -----------------------
__global__ void k_smax(const int* __restrict__ ids, int n) {
    int i = blockIdx.x * 256 + threadIdx.x;
    if (i < n) atomicMax(&g_smax[ids[i]], fenc(g_sim[i]));
}
__global__ void k_exp(const int* __restrict__ ids, int n) {
    int i = blockIdx.x * 256 + threadIdx.x;
    if (i < n) g_sim[i] = expf(g_sim[i] - fdec(g_smax[ids[i]]));
}
__global__ void k_gather(const float* __restrict__ ue) {
    int u    = blockIdx.x * 4 + (threadIdx.x >> 6);
    int lane = threadIdx.x & 63;
    if (u >= UU) return;
    int s = g_off[u], e = g_off[u + 1];

    float den = 0.0f;
    float4 acc = make_float4(0.f, 0.f, 0.f, 0.f);
    for (int r = s; r < e; r++) {
        int row = g_list[r];
        float ev = g_sim[row];                 // precomputed exp
        den += ev;
        float4 v = *(const float4*)&ue[(size_t)row * 256 + lane * 4];
        acc.x += ev * v.x; acc.y += ev * v.y; acc.z += ev * v.z; acc.w += ev * v.w;
    }
    float inv = (e > s) ? (1.0f / den) : 0.0f;
    acc.x *= inv; acc.y *= inv; acc.z *= inv; acc.w *= inv;
    *(float4*)&g_wsn[(size_t)u * 256 + lane * 4] = acc;
}

// ---------------- bf16 split GEMM (MODE 0/1), BM=64 BN=128, 4 CTA/SM -------------
// MODE 0: g_sim[row] += partial rowsum((A @ M) .* sess)
// MODE 1: g_D = wsn @ Bt + b1
template<int MODE>
__global__ __launch_bounds__(128, 4)
void k_mma(const float* __restrict__ Afp, const float* __restrict__ extra,
           const int* __restrict__ ids, float* __restrict__ outp, int nrows) {
    extern __shared__ __align__(16) char smem[];
    uint32_t sbase = (uint32_t)__cvta_generic_to_shared(smem);
    const int tid  = threadIdx.x;
    const int lane = tid & 31;
    const int wid  = tid >> 5;
    const int mw = wid >> 1, nw = wid & 1;
    const int blockRow = blockIdx.y * BM;
    const int colBase  = blockIdx.x * BN;

    const float* Ap = (MODE == 1) ? g_wsn : Afp;
    const __nv_bfloat16* Bth = (MODE == 0) ? g_Mth : g_Bth;
    const __nv_bfloat16* Btl = (MODE == 0) ? g_Mtl : g_Btl;

    float acc[2][8][4];
    #pragma unroll
    for (int t = 0; t < 2; t++)
        #pragma unroll
        for (int j = 0; j < 8; j++)
            #pragma unroll
            for (int c = 0; c < 4; c++) acc[t][j][c] = 0.0f;

    float4 ra[2][2];
    const int r0 = tid >> 2,         ch0 = tid & 3;
    const int r1 = (tid + 128) >> 2;
    auto ldgA = [&](int kt) {
        int g0 = blockRow + r0;
        bool a0 = g0 < nrows;
        const float4* s0 = (const float4*)(Ap + (size_t)(a0 ? g0 : 0) * HH + kt * BK + ch0 * 8);
        ra[0][0] = a0 ? s0[0] : make_float4(0.f, 0.f, 0.f, 0.f);
        ra[0][1] = a0 ? s0[1] : make_float4(0.f, 0.f, 0.f, 0.f);
        int g1 = blockRow + r1;
        bool a1 = g1 < nrows;
        const float4* s1 = (const float4*)(Ap + (size_t)(a1 ? g1 : 0) * HH + kt * BK + ch0 * 8);
        ra[1][0] = a1 ? s1[0] : make_float4(0.f, 0.f, 0.f, 0.f);
        ra[1][1] = a1 ? s1[1] : make_float4(0.f, 0.f, 0.f, 0.f);
    };
    auto stsA = [&](int s) {
        char* db = smem + s * STAGE_BYTES;
        #pragma unroll
        for (int l = 0; l < 2; l++) {
            int r = l ? r1 : r0;
            uint32_t dst = swz(r, ch0);
            uint32_t h0, h1, h2, h3, l0, l1, l2, l3;
            split2(ra[l][0].x, ra[l][0].y, h0, l0);
            split2(ra[l][0].z, ra[l][0].w, h1, l1);
            split2(ra[l][1].x, ra[l][1].y, h2, l2);
            split2(ra[l][1].z, ra[l][1].w, h3, l3);
            *(uint4*)(db + AH_OFF + dst) = make_uint4(h0, h1, h2, h3);
            *(uint4*)(db + AL_OFF + dst) = make_uint4(l0, l1, l2, l3);
        }
    };
    auto cpB = [&](int kt, int s) {
        uint32_t db = sbase + (uint32_t)s * STAGE_BYTES;
        #pragma unroll
        for (int l = 0; l < 4; l++) {
            int u = tid + l * 128;
            int r = u >> 2, ch = u & 3;
            size_t gb = (size_t)(colBase + r) * HH + kt * BK + ch * 8;
            uint32_t dst = swz(r, ch);
            cpa16(db + BH_OFF + dst, Bth + gb, true);
            cpa16(db + BL_OFF + dst, Btl + gb, true);
        }
        asm volatile("cp.async.commit_group;" ::: "memory");
    };

    ldgA(0); stsA(0);
    cpB(0, 0);
    ldgA(1);
    cpB(1, 1);

    const int NKT = HH / BK;   // 8
    for (int kt = 0; kt < NKT; kt++) {
        if (kt < NKT - 1) asm volatile("cp.async.wait_group 1;" ::: "memory");
        else              asm volatile("cp.async.wait_group 0;" ::: "memory");
        if (kt + 1 < NKT) stsA((kt + 1) & 1);
        __syncthreads();
        if (kt + 2 < NKT) ldgA(kt + 2);

        uint32_t sb = sbase + (uint32_t)(kt & 1) * STAGE_BYTES;
        #pragma unroll
        for (int k16 = 0; k16 < BK; k16 += 16) {
            uint32_t ah[2][4], al[2][4];
            #pragma unroll
            for (int t = 0; t < 2; t++) {
                int arow = mw * 32 + t * 16 + (lane & 15);
                int cb = (k16 >> 3) + (lane >> 4);
                uint32_t ao = swz(arow, cb);
                ldsm4(ah[t], sb + AH_OFF + ao);
                ldsm4(al[t], sb + AL_OFF + ao);
            }
            #pragma unroll
            for (int p = 0; p < 4; p++) {
                int brow = nw * 64 + p * 16 + (lane & 7) + ((lane >> 4) << 3);
                int cb = (k16 >> 3) + ((lane >> 3) & 1);
                uint32_t bo = swz(brow, cb);
                uint32_t bh[4], bl[4];
                ldsm4(bh, sb + BH_OFF + bo);
                ldsm4(bl, sb + BL_OFF + bo);
                #pragma unroll
                for (int t = 0; t < 2; t++)
                    #pragma unroll
                    for (int q = 0; q < 2; q++)
                        mma16816(acc[t][p * 2 + q], ah[t], &bh[2 * q]);
                #pragma unroll
                for (int t = 0; t < 2; t++)
                    #pragma unroll
                    for (int q = 0; q < 2; q++)
                        mma16816(acc[t][p * 2 + q], ah[t], &bl[2 * q]);
                #pragma unroll
                for (int t = 0; t < 2; t++)
                    #pragma unroll
                    for (int q = 0; q < 2; q++)
                        mma16816(acc[t][p * 2 + q], al[t], &bh[2 * q]);
            }
        }
        __syncthreads();
        if (kt + 2 < NKT) cpB(kt + 2, kt & 1);
    }

    const int lr = lane >> 2;
    const int lc = (lane & 3) * 2;

    if (MODE == 0) {
        float part[2][2] = {{0.f, 0.f}, {0.f, 0.f}};
        #pragma unroll
        for (int t = 0; t < 2; t++) {
            int row0 = blockRow + mw * 32 + t * 16 + lr;
            #pragma unroll
            for (int j = 0; j < 8; j++) {
                int col = colBase + nw * 64 + j * 8 + lc;
                if (row0 < nrows) {
                    float2 s = *(const float2*)&extra[(size_t)row0 * 256 + col];
                    part[t][0] += acc[t][j][0] * s.x + acc[t][j][1] * s.y;
                }
                if (row0 + 8 < nrows) {
                    float2 s = *(const float2*)&extra[(size_t)(row0 + 8) * 256 + col];
                    part[t][1] += acc[t][j][2] * s.x + acc[t][j][3] * s.y;
                }
            }
        }
        #pragma unroll
        for (int t = 0; t < 2; t++)
            #pragma unroll
            for (int h = 0; h < 2; h++) {
                part[t][h] += __shfl_xor_sync(0xffffffffu, part[t][h], 1);
                part[t][h] += __shfl_xor_sync(0xffffffffu, part[t][h], 2);
            }
        __syncthreads();
        float* red = (float*)smem;
        if ((lane & 3) == 0) {
            #pragma unroll
            for (int t = 0; t < 2; t++) {
                red[(mw * 32 + t * 16 + lr) * 2 + nw]     = part[t][0];
                red[(mw * 32 + t * 16 + lr + 8) * 2 + nw] = part[t][1];
            }
        }
        __syncthreads();
        if (tid < 64) {
            int row = blockRow + tid;
            if (row < nrows) {
                float s = red[tid * 2] + red[tid * 2 + 1];
                asm volatile("red.global.add.f32 [%0], %1;"
                             :: "l"(g_sim + row), "f"(s) : "memory");
            }
        }
    } else {
        #pragma unroll
        for (int t = 0; t < 2; t++)
            #pragma unroll
            for (int h = 0; h < 2; h++) {
                int row = blockRow + mw * 32 + t * 16 + lr + h * 8;
                if (row >= nrows) continue;
                #pragma unroll
                for (int j = 0; j < 8; j++) {
                    int col = colBase + nw * 64 + j * 8 + lc;
                    float2 b = *(const float2*)&extra[col];
                    float2 o;
                    o.x = acc[t][j][2 * h + 0] + b.x;
                    o.y = acc[t][j][2 * h + 1] + b.y;
                    *(float2*)&g_D[(size_t)row * 256 + col] = o;
                }
            }
    }
}

// ---------------- tf32 GEMM: P = ue @ C1 (raw, epilogue deferred) ----------------
__global__ __launch_bounds__(128, 4)
void k_tf(const float* __restrict__ Afp, float* __restrict__ outp, int nrows) {
    extern __shared__ __align__(16) char smem[];
    uint32_t sbase = (uint32_t)__cvta_generic_to_shared(smem);
    const int tid  = threadIdx.x;
    const int lane = tid & 31;
    const int wid  = tid >> 5;
    const int mw = wid >> 1, nw = wid & 1;     // warp tile 32 x 64
    const int blockRow = blockIdx.y * BM;
    const int colBase  = blockIdx.x * BN;

    float acc[2][8][4];
    #pragma unroll
    for (int t = 0; t < 2; t++)
        #pragma unroll
        for (int j = 0; j < 8; j++)
            #pragma unroll
            for (int c = 0; c < 4; c++) acc[t][j][c] = 0.0f;

    auto load_stage = [&](int kt, int s) {
        uint32_t db = sbase + (uint32_t)s * TF_STAGE;
        #pragma unroll
        for (int l = 0; l < 4; l++) {
            int u = tid + l * 128;
            int r = u >> 3, ch = u & 7;
            int grow = blockRow + r;
            bool v = grow < nrows;
            size_t ga = (size_t)(v ? grow : 0) * HH + kt * BK + ch * 4;
            cpa16(db + TF_A_OFF + swz128(r, ch), Afp + ga, v);
        }
        #pragma unroll
        for (int l = 0; l < 8; l++) {
            int u = tid + l * 128;
            int r = u >> 3, ch = u & 7;
            size_t gb = (size_t)(colBase + r) * HH + kt * BK + ch * 4;
            cpa16(db + TF_B_OFF + swz128(r, ch), g_C1f + gb, true);
        }
        asm volatile("cp.async.commit_group;" ::: "memory");
    };

    load_stage(0, 0);
    load_stage(1, 1);

    const int NKT = HH / BK;   // 8
    for (int kt = 0; kt < NKT; kt++) {
        if (kt < NKT - 1) asm volatile("cp.async.wait_group 1;" ::: "memory");
        else              asm volatile("cp.async.wait_group 0;" ::: "memory");
        __syncthreads();

        uint32_t sb = sbase + (uint32_t)(kt & 1) * TF_STAGE;
        #pragma unroll
        for (int k8 = 0; k8 < 4; k8++) {
            uint32_t av[2][4];
            #pragma unroll
            for (int t = 0; t < 2; t++) {
                int arow = mw * 32 + t * 16 + (lane & 7) + ((lane >> 3) & 1) * 8;
                int ch = k8 * 2 + (lane >> 4);
                ldsm4(av[t], sb + TF_A_OFF + swz128(arow, ch));
                av[t][0] = rna(av[t][0]); av[t][1] = rna(av[t][1]);
                av[t][2] = rna(av[t][2]); av[t][3] = rna(av[t][3]);
            }
            #pragma unroll
            for (int p = 0; p < 4; p++) {
                int brow = nw * 64 + p * 16 + (lane & 7) + ((lane >> 4) << 3);
                int bch = k8 * 2 + ((lane >> 3) & 1);
                uint32_t bv[4];
                ldsm4(bv, sb + TF_B_OFF + swz128(brow, bch));
                #pragma unroll
                for (int t = 0; t < 2; t++)
                    #pragma unroll
                    for (int q = 0; q < 2; q++)
                        mma_tf(acc[t][p * 2 + q], av[t], &bv[2 * q]);
            }
        }
        __syncthreads();
        if (kt + 2 < NKT) load_stage(kt + 2, kt & 1);
    }

    const int lr = lane >> 2;
    const int lc = (lane & 3) * 2;
    #pragma unroll
    for (int t = 0; t < 2; t++)
        #pragma unroll
        for (int h = 0; h < 2; h++) {
            int row = blockRow + mw * 32 + t * 16 + lr + h * 8;
            if (row >= nrows) continue;
            #pragma unroll
            for (int j = 0; j < 8; j++) {
                int col = colBase + nw * 64 + j * 8 + lc;
                float2 o;
                o.x = acc[t][j][2 * h + 0];
                o.y = acc[t][j][2 * h + 1];
                *(float2*)&outp[(size_t)row * 256 + col] = o;
            }
        }
}

// ---------------- join epilogue: out = relu(out + D[ids]) ------------------------
__global__ void k_epi(float* __restrict__ outp, const int* __restrict__ ids, int n) {
    int gid = blockIdx.x * 256 + threadIdx.x;   // n*64 threads
    int row = gid >> 6;
    int c4  = (gid & 63) * 4;
    if (row >= n) return;
    int uid = ids[row];
    float4 p = *(float4*)&outp[(size_t)row * 256 + c4];
    float4 d = *(const float4*)&g_D[(size_t)uid * 256 + c4];
    p.x = fmaxf(p.x + d.x, 0.0f);
    p.y = fmaxf(p.y + d.y, 0.0f);
    p.z = fmaxf(p.z + d.z, 0.0f);
    p.w = fmaxf(p.w + d.w, 0.0f);
    *(float4*)&outp[(size_t)row * 256 + c4] = p;
}

// ---------------- launch ----------------------------------------------------------
extern "C" void kernel_launch(void* const* d_in, const int* in_sizes, int n_in,
                              void* d_out, int out_size) {
    const float* sess = (const float*)d_in[0];
    const float* ue   = (const float*)d_in[1];
    const int*   ids  = (const int*)d_in[2];   // JAX x64 disabled: int32
    const float* Wq   = (const float*)d_in[3];
    const float* Wk   = (const float*)d_in[4];
    const float* Wv   = (const float*)d_in[5];
    const float* W1   = (const float*)d_in[6];
    const float* b1   = (const float*)d_in[7];
    float*       out  = (float*)d_out;
    int N = in_sizes[0] / HH;   // 200000

    static cudaStream_t s1, s2;
    static cudaEvent_t eZero, eCsr, eM0, eTf;
    static bool init = false;
    if (!init) {
        cudaFuncSetAttribute(k_mma<0>, cudaFuncAttributeMaxDynamicSharedMemorySize, NSTAGE * STAGE_BYTES);
        cudaFuncSetAttribute(k_mma<1>, cudaFuncAttributeMaxDynamicSharedMemorySize, NSTAGE * STAGE_BYTES);
        cudaFuncSetAttribute(k_tf,     cudaFuncAttributeMaxDynamicSharedMemorySize, NSTAGE * TF_STAGE);
        cudaStreamCreateWithFlags(&s1, cudaStreamNonBlocking);
        cudaStreamCreateWithFlags(&s2, cudaStreamNonBlocking);
        cudaEventCreateWithFlags(&eZero, cudaEventDisableTiming);
        cudaEventCreateWithFlags(&eCsr,  cudaEventDisableTiming);
        cudaEventCreateWithFlags(&eM0,   cudaEventDisableTiming);
        cudaEventCreateWithFlags(&eTf,   cudaEventDisableTiming);
        init = true;
    }

    dim3 gBig(2, (N + BM - 1) / BM);
    dim3 gU(2, (UU + BM - 1) / BM);

    // main stream: zero (both paths depend on it)
    k_zero<<<(NN + 255) / 256, 256>>>();

    // fork s1: CSR build (needs only ids + zeroed counters)
    cudaEventRecord(eZero, 0);
    cudaStreamWaitEvent(s1, eZero, 0);
    k_hist<<<(N + 255) / 256, 256, 0, s1>>>(ids, N);
    k_scan<<<1, 256, 0, s1>>>();
    k_fill<<<(N + 255) / 256, 256, 0, s1>>>(ids, N);
    cudaEventRecord(eCsr, s1);

    // main stream: weight prep + MODE 0 GEMM
    k_prepT<<<dim3(8, 8, 2), 256>>>(Wq, Wk, Wv, W1);
    k_prepBt<<<256, 256>>>(W1);
    k_mma<0><<<gBig, 128, NSTAGE * STAGE_BYTES>>>(ue, sess, ids, nullptr, N);

    // fork s2: tf32 GEMM P = ue @ C1 (independent of softmax path)
    cudaEventRecord(eM0, 0);
    cudaStreamWaitEvent(s2, eM0, 0);
    k_tf<<<gBig, 128, NSTAGE * TF_STAGE, s2>>>(ue, out, N);
    cudaEventRecord(eTf, s2);

    // main stream: softmax path + U-level GEMM
    k_smax<<<(N + 255) / 256, 256>>>(ids, N);
    k_exp<<<(N + 255) / 256, 256>>>(ids, N);
    cudaStreamWaitEvent(0, eCsr, 0);
    k_gather<<<(UU + 3) / 4, 256>>>(ue);
    k_mma<1><<<gU, 128, NSTAGE * STAGE_BYTES>>>(nullptr, b1, nullptr, nullptr, UU);

    // join: epilogue needs P (s2) and g_D (main)
    cudaStreamWaitEvent(0, eTf, 0);
    k_epi<<<(N * 64 + 255) / 256, 256>>>(out, ids, N);
}

// round 16
// speedup vs baseline: 2.9805x; 1.0188x over previous
#include <cuda_runtime.h>
#include <cuda_bf16.h>
#include <cuda_fp16.h>
#include <cstdint>

#define NN 200000
#define UU 20000
#define HH 256

#define BM 64
#define BN 128
#define BK 32
#define AH_OFF 0
#define AL_OFF 4096
#define BH_OFF 8192
#define BL_OFF 16384
#define STAGE_BYTES 24576
#define NSTAGE 2
// tf32 kernel stage: A 64x32 fp32 (8KB) + B 128x32 fp32 (16KB)
#define TF_A_OFF 0
#define TF_B_OFF 8192
#define TF_STAGE 24576

// ---------------- scratch (device globals) -------------------------------------
__device__ __align__(16) __nv_bfloat16 g_Mth [HH * HH], g_Mtl [HH * HH];  // M^T  hi/lo (n-major)
__device__ __align__(16) float         g_C1f [HH * HH];                    // C1^T tf32-rounded fp32 (n-major)
__device__ __align__(16) __nv_bfloat16 g_Bth [HH * HH], g_Btl [HH * HH];  // W1[:,H:]  (n-major) hi/lo
__device__ __align__(16) __half   g_P  [(size_t)NN * HH];  // raw tf32 product, fp16
__device__ __align__(16) float    g_wsn[UU * HH];   // normalized weighted sum (fp32)
__device__ __align__(16) float    g_D  [UU * HH];
__device__ __align__(16) float    g_sim[NN];
__device__ __align__(16) unsigned g_smax[UU];
__device__ int g_list[NN];          // CSR row lists
__device__ int g_off [UU + 1];
__device__ int g_cnt [UU];
__device__ int g_cnt2[UU];

// ---------------- helpers -------------------------------------------------------
__device__ __forceinline__ unsigned fenc(float f) {
    unsigned u = __float_as_uint(f);
    return (u & 0x80000000u) ? ~u : (u | 0x80000000u);
}
__device__ __forceinline__ float fdec(unsigned u) {
    return (u & 0x80000000u) ? __uint_as_float(u & 0x7FFFFFFFu) : __uint_as_float(~u);
}
__device__ __forceinline__ void ldsm4(uint32_t* r, uint32_t addr) {
    asm volatile("ldmatrix.sync.aligned.m8n8.x4.shared.b16 {%0,%1,%2,%3}, [%4];"
                 : "=r"(r[0]), "=r"(r[1]), "=r"(r[2]), "=r"(r[3]) : "r"(addr));
}
__device__ __forceinline__ void mma16816(float* c, const uint32_t* a, const uint32_t* b) {
    asm volatile("mma.sync.aligned.m16n8k16.row.col.f32.bf16.bf16.f32 "
                 "{%0,%1,%2,%3}, {%4,%5,%6,%7}, {%8,%9}, {%0,%1,%2,%3};"
                 : "+f"(c[0]), "+f"(c[1]), "+f"(c[2]), "+f"(c[3])
                 : "r"(a[0]), "r"(a[1]), "r"(a[2]), "r"(a[3]), "r"(b[0]), "r"(b[1]));
}
__device__ __forceinline__ void mma_tf(float* c, const uint32_t* a, const uint32_t* b) {
    asm volatile("mma.sync.aligned.m16n8k8.row.col.f32.tf32.tf32.f32 "
                 "{%0,%1,%2,%3}, {%4,%5,%6,%7}, {%8,%9}, {%0,%1,%2,%3};"
                 : "+f"(c[0]), "+f"(c[1]), "+f"(c[2]), "+f"(c[3])
                 : "r"(a[0]), "r"(a[1]), "r"(a[2]), "r"(a[3]), "r"(b[0]), "r"(b[1]));
}
__device__ __forceinline__ void cpa16(uint32_t dst, const void* src, bool v) {
    int sz = v ? 16 : 0;
    asm volatile("cp.async.cg.shared.global [%0], [%1], 16, %2;"
                 :: "r"(dst), "l"(src), "r"(sz));
}
__device__ __forceinline__ uint32_t swz(int row, int ch) {
    return (uint32_t)(row * 64 + ((ch ^ ((row >> 1) & 3)) * 16));
}
__device__ __forceinline__ uint32_t swz128(int row, int ch) {
    return (uint32_t)(row * 128 + ((ch ^ (row & 7)) * 16));
}
__device__ __forceinline__ void split2(float x, float y, uint32_t& hi, uint32_t& lo) {
    __nv_bfloat16 h0 = __float2bfloat16(x), h1 = __float2bfloat16(y);
    __nv_bfloat162 hp = __halves2bfloat162(h0, h1);
    hi = *(uint32_t*)&hp;
    __nv_bfloat16 l0 = __float2bfloat16(x - __bfloat162float(h0));
    __nv_bfloat16 l1 = __float2bfloat16(y - __bfloat162float(h1));
    __nv_bfloat162 lp = __halves2bfloat162(l0, l1);
    lo = *(uint32_t*)&lp;
}
__device__ __forceinline__ uint32_t rna(uint32_t x) {
    uint32_t y;
    asm("cvt.rna.tf32.f32 %0, %1;" : "=r"(y) : "f"(__uint_as_float(x)));
    return y;
}

// ---------------- init scratch -------------------------------------------------
__global__ void k_zero() {
    int idx = blockIdx.x * 256 + threadIdx.x;
    if (idx < NN) g_sim[idx] = 0.0f;
    if (idx < UU) { g_cnt[idx] = 0; g_cnt2[idx] = 0; g_smax[idx] = 0u; }
}

// ---------------- CSR build: hist -> scan -> fill --------------------------------
__global__ void k_hist(const int* __restrict__ ids, int n) {
    int i = blockIdx.x * 256 + threadIdx.x;
    if (i < n) atomicAdd(&g_cnt[ids[i]], 1);
}
__global__ void k_scan() {             // single block, 256 threads
    __shared__ int ps[256];
    const int C = (UU + 255) / 256;    // 79
    int t = threadIdx.x;
    int s = 0;
    for (int j = 0; j < C; j++) { int i = t * C + j; if (i < UU) s += g_cnt[i]; }
    ps[t] = s;
    __syncthreads();
    int acc = 0;
    for (int j = 0; j < t; j++) acc += ps[j];
    int run = acc;
    for (int j = 0; j < C; j++) {
        int i = t * C + j;
        if (i < UU) { g_off[i] = run; run += g_cnt[i]; }
    }
    if (t == 255) g_off[UU] = run;
}
__global__ void k_fill(const int* __restrict__ ids, int n) {
    int i = blockIdx.x * 256 + threadIdx.x;
    if (i < n) {
        int uid = ids[i];
        int pos = g_off[uid] + atomicAdd(&g_cnt2[uid], 1);
        g_list[pos] = i;
    }
}

// ---------------- coalesced precompute GEMMs -----------------------------------
// z==0: M[a,t]  = Wq[a,:]·Wk[t,:]      -> g_Mth/l [t*256+a] (bf16 hi/lo)
// z==1: C1[a,t] = Wv[a,:]·W1[t,0:256]  -> g_C1f  [t*256+a] (tf32-rounded fp32)
__global__ void k_prepT(const float* __restrict__ Wq, const float* __restrict__ Wk,
                        const float* __restrict__ Wv, const float* __restrict__ W1) {
    __shared__ float As[32 * 129];
    __shared__ float Bs[32 * 129];
    int z = blockIdx.z;
    int tid = threadIdx.x;
    int abase = blockIdx.y * 32;
    int tbase = blockIdx.x * 32;
    const float* Ag = z ? Wv : Wq;
    int tx = tid & 31, ty = tid >> 5;
    float acc[4] = {0.f, 0.f, 0.f, 0.f};

    for (int kt = 0; kt < 256; kt += 128) {
        #pragma unroll
        for (int i = 0; i < 16; i++) {
            int f = tid + i * 256;
            int r = f >> 7, c = f & 127;
            As[r * 129 + c] = Ag[(abase + r) * 256 + kt + c];
            Bs[r * 129 + c] = z ? W1[(tbase + r) * 512 + kt + c]
                                : Wk[(tbase + r) * 256 + kt + c];
        }
        __syncthreads();
        #pragma unroll 4
        for (int k = 0; k < 128; k++) {
            float av = As[tx * 129 + k];
            #pragma unroll
            for (int j = 0; j < 4; j++) acc[j] += av * Bs[(ty + 8 * j) * 129 + k];
        }
        __syncthreads();
    }
    int a = abase + tx;
    #pragma unroll
    for (int j = 0; j < 4; j++) {
        int t = tbase + ty + 8 * j;
        if (z == 0) {
            __nv_bfloat16 h = __float2bfloat16(acc[j]);
            __nv_bfloat16 l = __float2bfloat16(acc[j] - __bfloat162float(h));
            g_Mth[t * 256 + a] = h;
            g_Mtl[t * 256 + a] = l;
        } else {
            g_C1f[t * 256 + a] = __uint_as_float(rna(__float_as_uint(acc[j])));
        }
    }
}

// Bt (n-major, bf16 hi/lo): g_Bth[j*256+k] = W1[j*512+256+k]
__global__ void k_prepBt(const float* __restrict__ W1) {
    int j = blockIdx.x, k = threadIdx.x;
    float v = W1[j * 512 + 256 + k];
    __nv_bfloat16 h = __float2bfloat16(v);
    g_Bth[j * 256 + k] = h;
    g_Btl[j * 256 + k] = __float2bfloat16(v - __bfloat162float(h));
}

// ---------------- softmax: segment max, exp, 1-pass gather -----------------------
__global__ void k_smax(const int* __restrict__ ids, int n) {
    int i = blockIdx.x * 256 + threadIdx.x;
    if (i < n) atomicMax(&g_smax[ids[i]], fenc(g_sim[i]));
}
__global__ void k_exp(const int* __restrict__ ids, int n) {
    int i = blockIdx.x * 256 + threadIdx.x;
    if (i < n) g_sim[i] = expf(g_sim[i] - fdec(g_smax[ids[i]]));
}
__global__ void k_gather(const float* __restrict__ ue) {
    int u    = blockIdx.x * 4 + (threadIdx.x >> 6);
    int lane = threadIdx.x & 63;
    if (u >= UU) return;
    int s = g_off[u], e = g_off[u + 1];

    float den = 0.0f;
    float4 acc = make_float4(0.f, 0.f, 0.f, 0.f);
    for (int r = s; r < e; r++) {
        int row = g_list[r];
        float ev = g_sim[row];                 // precomputed exp
        den += ev;
        float4 v = *(const float4*)&ue[(size_t)row * 256 + lane * 4];
        acc.x += ev * v.x; acc.y += ev * v.y; acc.z += ev * v.z; acc.w += ev * v.w;
    }
    float inv = (e > s) ? (1.0f / den) : 0.0f;
    acc.x *= inv; acc.y *= inv; acc.z *= inv; acc.w *= inv;
    *(float4*)&g_wsn[(size_t)u * 256 + lane * 4] = acc;
}

// ---------------- bf16 split GEMM (MODE 0/1), BM=64 BN=128, 4 CTA/SM -------------
// MODE 0: g_sim[row] += partial rowsum((A @ M) .* sess)
// MODE 1: g_D = wsn @ Bt + b1
template<int MODE>
__global__ __launch_bounds__(128, 4)
void k_mma(const float* __restrict__ Afp, const float* __restrict__ extra,
           const int* __restrict__ ids, float* __restrict__ outp, int nrows) {
    extern __shared__ __align__(16) char smem[];
    uint32_t sbase = (uint32_t)__cvta_generic_to_shared(smem);
    const int tid  = threadIdx.x;
    const int lane = tid & 31;
    const int wid  = tid >> 5;
    const int mw = wid >> 1, nw = wid & 1;
    const int blockRow = blockIdx.y * BM;
    const int colBase  = blockIdx.x * BN;

    const float* Ap = (MODE == 1) ? g_wsn : Afp;
    const __nv_bfloat16* Bth = (MODE == 0) ? g_Mth : g_Bth;
    const __nv_bfloat16* Btl = (MODE == 0) ? g_Mtl : g_Btl;

    float acc[2][8][4];
    #pragma unroll
    for (int t = 0; t < 2; t++)
        #pragma unroll
        for (int j = 0; j < 8; j++)
            #pragma unroll
            for (int c = 0; c < 4; c++) acc[t][j][c] = 0.0f;

    float4 ra[2][2];
    const int r0 = tid >> 2,         ch0 = tid & 3;
    const int r1 = (tid + 128) >> 2;
    auto ldgA = [&](int kt) {
        int g0 = blockRow + r0;
        bool a0 = g0 < nrows;
        const float4* s0 = (const float4*)(Ap + (size_t)(a0 ? g0 : 0) * HH + kt * BK + ch0 * 8);
        ra[0][0] = a0 ? s0[0] : make_float4(0.f, 0.f, 0.f, 0.f);
        ra[0][1] = a0 ? s0[1] : make_float4(0.f, 0.f, 0.f, 0.f);
        int g1 = blockRow + r1;
        bool a1 = g1 < nrows;
        const float4* s1 = (const float4*)(Ap + (size_t)(a1 ? g1 : 0) * HH + kt * BK + ch0 * 8);
        ra[1][0] = a1 ? s1[0] : make_float4(0.f, 0.f, 0.f, 0.f);
        ra[1][1] = a1 ? s1[1] : make_float4(0.f, 0.f, 0.f, 0.f);
    };
    auto stsA = [&](int s) {
        char* db = smem + s * STAGE_BYTES;
        #pragma unroll
        for (int l = 0; l < 2; l++) {
            int r = l ? r1 : r0;
            uint32_t dst = swz(r, ch0);
            uint32_t h0, h1, h2, h3, l0, l1, l2, l3;
            split2(ra[l][0].x, ra[l][0].y, h0, l0);
            split2(ra[l][0].z, ra[l][0].w, h1, l1);
            split2(ra[l][1].x, ra[l][1].y, h2, l2);
            split2(ra[l][1].z, ra[l][1].w, h3, l3);
            *(uint4*)(db + AH_OFF + dst) = make_uint4(h0, h1, h2, h3);
            *(uint4*)(db + AL_OFF + dst) = make_uint4(l0, l1, l2, l3);
        }
    };
    auto cpB = [&](int kt, int s) {
        uint32_t db = sbase + (uint32_t)s * STAGE_BYTES;
        #pragma unroll
        for (int l = 0; l < 4; l++) {
            int u = tid + l * 128;
            int r = u >> 2, ch = u & 3;
            size_t gb = (size_t)(colBase + r) * HH + kt * BK + ch * 8;
            uint32_t dst = swz(r, ch);
            cpa16(db + BH_OFF + dst, Bth + gb, true);
            cpa16(db + BL_OFF + dst, Btl + gb, true);
        }
        asm volatile("cp.async.commit_group;" ::: "memory");
    };

    ldgA(0); stsA(0);
    cpB(0, 0);
    ldgA(1);
    cpB(1, 1);

    const int NKT = HH / BK;   // 8
    for (int kt = 0; kt < NKT; kt++) {
        if (kt < NKT - 1) asm volatile("cp.async.wait_group 1;" ::: "memory");
        else              asm volatile("cp.async.wait_group 0;" ::: "memory");
        if (kt + 1 < NKT) stsA((kt + 1) & 1);
        __syncthreads();
        if (kt + 2 < NKT) ldgA(kt + 2);

        uint32_t sb = sbase + (uint32_t)(kt & 1) * STAGE_BYTES;
        #pragma unroll
        for (int k16 = 0; k16 < BK; k16 += 16) {
            uint32_t ah[2][4], al[2][4];
            #pragma unroll
            for (int t = 0; t < 2; t++) {
                int arow = mw * 32 + t * 16 + (lane & 15);
                int cb = (k16 >> 3) + (lane >> 4);
                uint32_t ao = swz(arow, cb);
                ldsm4(ah[t], sb + AH_OFF + ao);
                ldsm4(al[t], sb + AL_OFF + ao);
            }
            #pragma unroll
            for (int p = 0; p < 4; p++) {
                int brow = nw * 64 + p * 16 + (lane & 7) + ((lane >> 4) << 3);
                int cb = (k16 >> 3) + ((lane >> 3) & 1);
                uint32_t bo = swz(brow, cb);
                uint32_t bh[4], bl[4];
                ldsm4(bh, sb + BH_OFF + bo);
                ldsm4(bl, sb + BL_OFF + bo);
                #pragma unroll
                for (int t = 0; t < 2; t++)
                    #pragma unroll
                    for (int q = 0; q < 2; q++)
                        mma16816(acc[t][p * 2 + q], ah[t], &bh[2 * q]);
                #pragma unroll
                for (int t = 0; t < 2; t++)
                    #pragma unroll
                    for (int q = 0; q < 2; q++)
                        mma16816(acc[t][p * 2 + q], ah[t], &bl[2 * q]);
                #pragma unroll
                for (int t = 0; t < 2; t++)
                    #pragma unroll
                    for (int q = 0; q < 2; q++)
                        mma16816(acc[t][p * 2 + q], al[t], &bh[2 * q]);
            }
        }
        __syncthreads();
        if (kt + 2 < NKT) cpB(kt + 2, kt & 1);
    }

    const int lr = lane >> 2;
    const int lc = (lane & 3) * 2;

    if (MODE == 0) {
        float part[2][2] = {{0.f, 0.f}, {0.f, 0.f}};
        #pragma unroll
        for (int t = 0; t < 2; t++) {
            int row0 = blockRow + mw * 32 + t * 16 + lr;
            #pragma unroll
            for (int j = 0; j < 8; j++) {
                int col = colBase + nw * 64 + j * 8 + lc;
                if (row0 < nrows) {
                    float2 s = *(const float2*)&extra[(size_t)row0 * 256 + col];
                    part[t][0] += acc[t][j][0] * s.x + acc[t][j][1] * s.y;
                }
                if (row0 + 8 < nrows) {
                    float2 s = *(const float2*)&extra[(size_t)(row0 + 8) * 256 + col];
                    part[t][1] += acc[t][j][2] * s.x + acc[t][j][3] * s.y;
                }
            }
        }
        #pragma unroll
        for (int t = 0; t < 2; t++)
            #pragma unroll
            for (int h = 0; h < 2; h++) {
                part[t][h] += __shfl_xor_sync(0xffffffffu, part[t][h], 1);
                part[t][h] += __shfl_xor_sync(0xffffffffu, part[t][h], 2);
            }
        __syncthreads();
        float* red = (float*)smem;
        if ((lane & 3) == 0) {
            #pragma unroll
            for (int t = 0; t < 2; t++) {
                red[(mw * 32 + t * 16 + lr) * 2 + nw]     = part[t][0];
                red[(mw * 32 + t * 16 + lr + 8) * 2 + nw] = part[t][1];
            }
        }
        __syncthreads();
        if (tid < 64) {
            int row = blockRow + tid;
            if (row < nrows) {
                float s = red[tid * 2] + red[tid * 2 + 1];
                asm volatile("red.global.add.f32 [%0], %1;"
                             :: "l"(g_sim + row), "f"(s) : "memory");
            }
        }
    } else {
        #pragma unroll
        for (int t = 0; t < 2; t++)
            #pragma unroll
            for (int h = 0; h < 2; h++) {
                int row = blockRow + mw * 32 + t * 16 + lr + h * 8;
                if (row >= nrows) continue;
                #pragma unroll
                for (int j = 0; j < 8; j++) {
                    int col = colBase + nw * 64 + j * 8 + lc;
                    float2 b = *(const float2*)&extra[col];
                    float2 o;
                    o.x = acc[t][j][2 * h + 0] + b.x;
                    o.y = acc[t][j][2 * h + 1] + b.y;
                    *(float2*)&g_D[(size_t)row * 256 + col] = o;
                }
            }
    }
}

// ---------------- tf32 GEMM: g_P = ue @ C1 (fp16, epilogue deferred) -------------
__global__ __launch_bounds__(128, 4)
void k_tf(const float* __restrict__ Afp, int nrows) {
    extern __shared__ __align__(16) char smem[];
    uint32_t sbase = (uint32_t)__cvta_generic_to_shared(smem);
    const int tid  = threadIdx.x;
    const int lane = tid & 31;
    const int wid  = tid >> 5;
    const int mw = wid >> 1, nw = wid & 1;     // warp tile 32 x 64
    const int blockRow = blockIdx.y * BM;
    const int colBase  = blockIdx.x * BN;

    float acc[2][8][4];
    #pragma unroll
    for (int t = 0; t < 2; t++)
        #pragma unroll
        for (int j = 0; j < 8; j++)
            #pragma unroll
            for (int c = 0; c < 4; c++) acc[t][j][c] = 0.0f;

    auto load_stage = [&](int kt, int s) {
        uint32_t db = sbase + (uint32_t)s * TF_STAGE;
        #pragma unroll
        for (int l = 0; l < 4; l++) {
            int u = tid + l * 128;
            int r = u >> 3, ch = u & 7;
            int grow = blockRow + r;
            bool v = grow < nrows;
            size_t ga = (size_t)(v ? grow : 0) * HH + kt * BK + ch * 4;
            cpa16(db + TF_A_OFF + swz128(r, ch), Afp + ga, v);
        }
        #pragma unroll
        for (int l = 0; l < 8; l++) {
            int u = tid + l * 128;
            int r = u >> 3, ch = u & 7;
            size_t gb = (size_t)(colBase + r) * HH + kt * BK + ch * 4;
            cpa16(db + TF_B_OFF + swz128(r, ch), g_C1f + gb, true);
        }
        asm volatile("cp.async.commit_group;" ::: "memory");
    };

    load_stage(0, 0);
    load_stage(1, 1);

    const int NKT = HH / BK;   // 8
    for (int kt = 0; kt < NKT; kt++) {
        if (kt < NKT - 1) asm volatile("cp.async.wait_group 1;" ::: "memory");
        else              asm volatile("cp.async.wait_group 0;" ::: "memory");
        __syncthreads();

        uint32_t sb = sbase + (uint32_t)(kt & 1) * TF_STAGE;
        #pragma unroll
        for (int k8 = 0; k8 < 4; k8++) {
            uint32_t av[2][4];
            #pragma unroll
            for (int t = 0; t < 2; t++) {
                int arow = mw * 32 + t * 16 + (lane & 7) + ((lane >> 3) & 1) * 8;
                int ch = k8 * 2 + (lane >> 4);
                ldsm4(av[t], sb + TF_A_OFF + swz128(arow, ch));
                av[t][0] = rna(av[t][0]); av[t][1] = rna(av[t][1]);
                av[t][2] = rna(av[t][2]); av[t][3] = rna(av[t][3]);
            }
            #pragma unroll
            for (int p = 0; p < 4; p++) {
                int brow = nw * 64 + p * 16 + (lane & 7) + ((lane >> 4) << 3);
                int bch = k8 * 2 + ((lane >> 3) & 1);
                uint32_t bv[4];
                ldsm4(bv, sb + TF_B_OFF + swz128(brow, bch));
                #pragma unroll
                for (int t = 0; t < 2; t++)
                    #pragma unroll
                    for (int q = 0; q < 2; q++)
                        mma_tf(acc[t][p * 2 + q], av[t], &bv[2 * q]);
            }
        }
        __syncthreads();
        if (kt + 2 < NKT) load_stage(kt + 2, kt & 1);
    }

    const int lr = lane >> 2;
    const int lc = (lane & 3) * 2;
    #pragma unroll
    for (int t = 0; t < 2; t++)
        #pragma unroll
        for (int h = 0; h < 2; h++) {
            int row = blockRow + mw * 32 + t * 16 + lr + h * 8;
            if (row >= nrows) continue;
            #pragma unroll
            for (int j = 0; j < 8; j++) {
                int col = colBase + nw * 64 + j * 8 + lc;
                __half2 hp = __floats2half2_rn(acc[t][j][2 * h + 0], acc[t][j][2 * h + 1]);
                *(__half2*)&g_P[(size_t)row * 256 + col] = hp;
            }
        }
}

// ---------------- join epilogue: out = relu(P + D[ids]) --------------------------
__global__ void k_epi(float* __restrict__ outp, const int* __restrict__ ids, int n) {
    int gid = blockIdx.x * 256 + threadIdx.x;   // n*64 threads
    int row = gid >> 6;
    int c4  = (gid & 63) * 4;
    if (row >= n) return;
    int uid = ids[row];
    float2 p01 = __half22float2(*(const __half2*)&g_P[(size_t)row * 256 + c4]);
    float2 p23 = __half22float2(*(const __half2*)&g_P[(size_t)row * 256 + c4 + 2]);
    float4 d = *(const float4*)&g_D[(size_t)uid * 256 + c4];
    float4 o;
    o.x = fmaxf(p01.x + d.x, 0.0f);
    o.y = fmaxf(p01.y + d.y, 0.0f);
    o.z = fmaxf(p23.x + d.z, 0.0f);
    o.w = fmaxf(p23.y + d.w, 0.0f);
    *(float4*)&outp[(size_t)row * 256 + c4] = o;
}

// ---------------- launch ----------------------------------------------------------
extern "C" void kernel_launch(void* const* d_in, const int* in_sizes, int n_in,
                              void* d_out, int out_size) {
    const float* sess = (const float*)d_in[0];
    const float* ue   = (const float*)d_in[1];
    const int*   ids  = (const int*)d_in[2];   // JAX x64 disabled: int32
    const float* Wq   = (const float*)d_in[3];
    const float* Wk   = (const float*)d_in[4];
    const float* Wv   = (const float*)d_in[5];
    const float* W1   = (const float*)d_in[6];
    const float* b1   = (const float*)d_in[7];
    float*       out  = (float*)d_out;
    int N = in_sizes[0] / HH;   // 200000

    static cudaStream_t s1, s2;
    static cudaEvent_t eZero, eCsr, ePrep, eTf;
    static bool init = false;
    if (!init) {
        cudaFuncSetAttribute(k_mma<0>, cudaFuncAttributeMaxDynamicSharedMemorySize, NSTAGE * STAGE_BYTES);
        cudaFuncSetAttribute(k_mma<1>, cudaFuncAttributeMaxDynamicSharedMemorySize, NSTAGE * STAGE_BYTES);
        cudaFuncSetAttribute(k_tf,     cudaFuncAttributeMaxDynamicSharedMemorySize, NSTAGE * TF_STAGE);
        cudaStreamCreateWithFlags(&s1, cudaStreamNonBlocking);
        cudaStreamCreateWithFlags(&s2, cudaStreamNonBlocking);
        cudaEventCreateWithFlags(&eZero, cudaEventDisableTiming);
        cudaEventCreateWithFlags(&eCsr,  cudaEventDisableTiming);
        cudaEventCreateWithFlags(&ePrep, cudaEventDisableTiming);
        cudaEventCreateWithFlags(&eTf,   cudaEventDisableTiming);
        init = true;
    }

    dim3 gBig(2, (N + BM - 1) / BM);
    dim3 gU(2, (UU + BM - 1) / BM);

    // main stream: zero
    k_zero<<<(NN + 255) / 256, 256>>>();

    // fork s1: CSR build (needs only ids + zeroed counters)
    cudaEventRecord(eZero, 0);
    cudaStreamWaitEvent(s1, eZero, 0);
    k_hist<<<(N + 255) / 256, 256, 0, s1>>>(ids, N);
    k_scan<<<1, 256, 0, s1>>>();
    k_fill<<<(N + 255) / 256, 256, 0, s1>>>(ids, N);
    cudaEventRecord(eCsr, s1);

    // main stream: weight prep
    k_prepT<<<dim3(8, 8, 2), 256>>>(Wq, Wk, Wv, W1);
    k_prepBt<<<256, 256>>>(W1);

    // fork s2: tf32 GEMM (needs only prep + ue) — concurrent with MODE 0 (L2 ue sharing)
    cudaEventRecord(ePrep, 0);
    cudaStreamWaitEvent(s2, ePrep, 0);
    k_tf<<<gBig, 128, NSTAGE * TF_STAGE, s2>>>(ue, N);
    cudaEventRecord(eTf, s2);

    // main stream: MODE 0 GEMM + softmax path + U-level GEMM
    k_mma<0><<<gBig, 128, NSTAGE * STAGE_BYTES>>>(ue, sess, ids, nullptr, N);
    k_smax<<<(N + 255) / 256, 256>>>(ids, N);
    k_exp<<<(N + 255) / 256, 256>>>(ids, N);
    cudaStreamWaitEvent(0, eCsr, 0);
    k_gather<<<(UU + 3) / 4, 256>>>(ue);
    k_mma<1><<<gU, 128, NSTAGE * STAGE_BYTES>>>(nullptr, b1, nullptr, nullptr, UU);

    // join: epilogue needs P (s2) and g_D (main)
    cudaStreamWaitEvent(0, eTf, 0);
    k_epi<<<(N * 64 + 255) / 256, 256>>>(out, ids, N);
}

// round 17
// speedup vs baseline: 3.0016x; 1.0071x over previous
#include <cuda_runtime.h>
#include <cuda_bf16.h>
#include <cuda_fp16.h>
#include <cstdint>

#define NN 200000
#define UU 20000
#define HH 256

#define BM 64
#define BN 128
#define BK 32
#define AH_OFF 0
#define AL_OFF 4096
#define BH_OFF 8192
#define BL_OFF 16384
#define STAGE_BYTES 24576
#define NSTAGE 2
// tf32 kernel stage: A 64x32 fp32 (8KB) + B 128x32 fp32 (16KB)
#define TF_A_OFF 0
#define TF_B_OFF 8192
#define TF_STAGE 24576

// ---------------- scratch (device globals) -------------------------------------
__device__ __align__(16) __nv_bfloat16 g_Mth [HH * HH], g_Mtl [HH * HH];  // M^T  hi/lo (n-major)
__device__ __align__(16) float         g_C1f [HH * HH];                    // C1^T tf32-rounded fp32 (n-major)
__device__ __align__(16) __nv_bfloat16 g_Bth [HH * HH], g_Btl [HH * HH];  // W1[:,H:]  (n-major) hi/lo
__device__ __align__(16) __half   g_P  [(size_t)NN * HH];  // raw tf32 product, fp16
__device__ __align__(16) float    g_wsn[UU * HH];   // normalized weighted sum (fp32)
__device__ __align__(16) float    g_D  [UU * HH];
__device__ __align__(16) float    g_sim[NN];
__device__ __align__(16) unsigned g_smax[UU];
__device__ int g_list[NN];          // CSR row lists
__device__ int g_off [UU + 1];
__device__ int g_cnt [UU];
__device__ int g_cnt2[UU];

// ---------------- helpers -------------------------------------------------------
__device__ __forceinline__ unsigned fenc(float f) {
    unsigned u = __float_as_uint(f);
    return (u & 0x80000000u) ? ~u : (u | 0x80000000u);
}
__device__ __forceinline__ float fdec(unsigned u) {
    return (u & 0x80000000u) ? __uint_as_float(u & 0x7FFFFFFFu) : __uint_as_float(~u);
}
__device__ __forceinline__ void ldsm4(uint32_t* r, uint32_t addr) {
    asm volatile("ldmatrix.sync.aligned.m8n8.x4.shared.b16 {%0,%1,%2,%3}, [%4];"
                 : "=r"(r[0]), "=r"(r[1]), "=r"(r[2]), "=r"(r[3]) : "r"(addr));
}
__device__ __forceinline__ void mma16816(float* c, const uint32_t* a, const uint32_t* b) {
    asm volatile("mma.sync.aligned.m16n8k16.row.col.f32.bf16.bf16.f32 "
                 "{%0,%1,%2,%3}, {%4,%5,%6,%7}, {%8,%9}, {%0,%1,%2,%3};"
                 : "+f"(c[0]), "+f"(c[1]), "+f"(c[2]), "+f"(c[3])
                 : "r"(a[0]), "r"(a[1]), "r"(a[2]), "r"(a[3]), "r"(b[0]), "r"(b[1]));
}
__device__ __forceinline__ void mma_tf(float* c, const uint32_t* a, const uint32_t* b) {
    asm volatile("mma.sync.aligned.m16n8k8.row.col.f32.tf32.tf32.f32 "
                 "{%0,%1,%2,%3}, {%4,%5,%6,%7}, {%8,%9}, {%0,%1,%2,%3};"
                 : "+f"(c[0]), "+f"(c[1]), "+f"(c[2]), "+f"(c[3])
                 : "r"(a[0]), "r"(a[1]), "r"(a[2]), "r"(a[3]), "r"(b[0]), "r"(b[1]));
}
__device__ __forceinline__ void cpa16(uint32_t dst, const void* src, bool v) {
    int sz = v ? 16 : 0;
    asm volatile("cp.async.cg.shared.global [%0], [%1], 16, %2;"
                 :: "r"(dst), "l"(src), "r"(sz));
}
__device__ __forceinline__ uint32_t swz(int row, int ch) {
    return (uint32_t)(row * 64 + ((ch ^ ((row >> 1) & 3)) * 16));
}
__device__ __forceinline__ uint32_t swz128(int row, int ch) {
    return (uint32_t)(row * 128 + ((ch ^ (row & 7)) * 16));
}
__device__ __forceinline__ void split2(float x, float y, uint32_t& hi, uint32_t& lo) {
    __nv_bfloat16 h0 = __float2bfloat16(x), h1 = __float2bfloat16(y);
    __nv_bfloat162 hp = __halves2bfloat162(h0, h1);
    hi = *(uint32_t*)&hp;
    __nv_bfloat16 l0 = __float2bfloat16(x - __bfloat162float(h0));
    __nv_bfloat16 l1 = __float2bfloat16(y - __bfloat162float(h1));
    __nv_bfloat162 lp = __halves2bfloat162(l0, l1);
    lo = *(uint32_t*)&lp;
}
__device__ __forceinline__ uint32_t rna(uint32_t x) {
    uint32_t y;
    asm("cvt.rna.tf32.f32 %0, %1;" : "=r"(y) : "f"(__uint_as_float(x)));
    return y;
}

// ---------------- init scratch -------------------------------------------------
__global__ void k_zero() {
    int idx = blockIdx.x * 256 + threadIdx.x;
    if (idx < NN) g_sim[idx] = 0.0f;
    if (idx < UU) { g_cnt[idx] = 0; g_cnt2[idx] = 0; g_smax[idx] = 0u; }
}

// ---------------- CSR build: hist -> scan -> fill --------------------------------
__global__ void k_hist(const int* __restrict__ ids, int n) {
    int i = blockIdx.x * 256 + threadIdx.x;
    if (i < n) atomicAdd(&g_cnt[ids[i]], 1);
}
__global__ void k_scan() {             // single block, 256 threads
    __shared__ int ps[256];
    const int C = (UU + 255) / 256;    // 79
    int t = threadIdx.x;
    int s = 0;
    for (int j = 0; j < C; j++) { int i = t * C + j; if (i < UU) s += g_cnt[i]; }
    ps[t] = s;
    __syncthreads();
    int acc = 0;
    for (int j = 0; j < t; j++) acc += ps[j];
    int run = acc;
    for (int j = 0; j < C; j++) {
        int i = t * C + j;
        if (i < UU) { g_off[i] = run; run += g_cnt[i]; }
    }
    if (t == 255) g_off[UU] = run;
}
__global__ void k_fill(const int* __restrict__ ids, int n) {
    int i = blockIdx.x * 256 + threadIdx.x;
    if (i < n) {
        int uid = ids[i];
        int pos = g_off[uid] + atomicAdd(&g_cnt2[uid], 1);
        g_list[pos] = i;
    }
}

// ---------------- coalesced precompute GEMMs -----------------------------------
// z==0: M[a,t]  = Wq[a,:]·Wk[t,:]      -> g_Mth/l [t*256+a] (bf16 hi/lo)
// z==1: C1[a,t] = Wv[a,:]·W1[t,0:256]  -> g_C1f  [t*256+a] (tf32-rounded fp32)
// z==2: Bt[j*256+k] = W1[j*512+256+k]  -> g_Bth/l (bf16 hi/lo)
__global__ void k_prepT(const float* __restrict__ Wq, const float* __restrict__ Wk,
                        const float* __restrict__ Wv, const float* __restrict__ W1) {
    int z = blockIdx.z;
    int tid = threadIdx.x;
    if (z == 2) {
        // 64 blocks (8x8) x 256 thr x 4 elems: j block = y, k block = x
        int jb = blockIdx.y * 32, kb = blockIdx.x * 32;
        #pragma unroll
        for (int e = 0; e < 4; e++) {
            int f = tid + e * 256;
            int j = jb + (f >> 5), k = kb + (f & 31);
            float v = W1[j * 512 + 256 + k];
            __nv_bfloat16 h = __float2bfloat16(v);
            g_Bth[j * 256 + k] = h;
            g_Btl[j * 256 + k] = __float2bfloat16(v - __bfloat162float(h));
        }
        return;
    }
    __shared__ float As[32 * 129];
    __shared__ float Bs[32 * 129];
    int abase = blockIdx.y * 32;
    int tbase = blockIdx.x * 32;
    const float* Ag = z ? Wv : Wq;
    int tx = tid & 31, ty = tid >> 5;
    float acc[4] = {0.f, 0.f, 0.f, 0.f};

    for (int kt = 0; kt < 256; kt += 128) {
        #pragma unroll
        for (int i = 0; i < 16; i++) {
            int f = tid + i * 256;
            int r = f >> 7, c = f & 127;
            As[r * 129 + c] = Ag[(abase + r) * 256 + kt + c];
            Bs[r * 129 + c] = z ? W1[(tbase + r) * 512 + kt + c]
                                : Wk[(tbase + r) * 256 + kt + c];
        }
        __syncthreads();
        #pragma unroll 4
        for (int k = 0; k < 128; k++) {
            float av = As[tx * 129 + k];
            #pragma unroll
            for (int j = 0; j < 4; j++) acc[j] += av * Bs[(ty + 8 * j) * 129 + k];
        }
        __syncthreads();
    }
    int a = abase + tx;
    #pragma unroll
    for (int j = 0; j < 4; j++) {
        int t = tbase + ty + 8 * j;
        if (z == 0) {
            __nv_bfloat16 h = __float2bfloat16(acc[j]);
            __nv_bfloat16 l = __float2bfloat16(acc[j] - __bfloat162float(h));
            g_Mth[t * 256 + a] = h;
            g_Mtl[t * 256 + a] = l;
        } else {
            g_C1f[t * 256 + a] = __uint_as_float(rna(__float_as_uint(acc[j])));
        }
    }
}

// ---------------- softmax: segment max, 1-pass gather (exp inline) ---------------
__global__ void k_smax(const int* __restrict__ ids, int n) {
    int i = blockIdx.x * 256 + threadIdx.x;
    if (i < n) atomicMax(&g_smax[ids[i]], fenc(g_sim[i]));
}
__global__ void k_gather(const float* __restrict__ ue) {
    int u    = blockIdx.x * 4 + (threadIdx.x >> 6);
    int lane = threadIdx.x & 63;
    if (u >= UU) return;
    int s = g_off[u], e = g_off[u + 1];
    float mx = fdec(g_smax[u]);

    float den = 0.0f;
    float4 acc = make_float4(0.f, 0.f, 0.f, 0.f);
    for (int r = s; r < e; r++) {
        int row = g_list[r];
        float ev = expf(g_sim[row] - mx);
        den += ev;
        float4 v = *(const float4*)&ue[(size_t)row * 256 + lane * 4];
        acc.x += ev * v.x; acc.y += ev * v.y; acc.z += ev * v.z; acc.w += ev * v.w;
    }
    float inv = (e > s) ? (1.0f / den) : 0.0f;
    acc.x *= inv; acc.y *= inv; acc.z *= inv; acc.w *= inv;
    *(float4*)&g_wsn[(size_t)u * 256 + lane * 4] = acc;
}

// ---------------- bf16 split GEMM (MODE 0/1), BM=64 BN=128, 4 CTA/SM -------------
// MODE 0: g_sim[row] += partial rowsum((A @ M) .* sess)
// MODE 1: g_D = wsn @ Bt + b1
template<int MODE>
__global__ __launch_bounds__(128, 4)
void k_mma(const float* __restrict__ Afp, const float* __restrict__ extra,
           const int* __restrict__ ids, float* __restrict__ outp, int nrows) {
    extern __shared__ __align__(16) char smem[];
    uint32_t sbase = (uint32_t)__cvta_generic_to_shared(smem);
    const int tid  = threadIdx.x;
    const int lane = tid & 31;
    const int wid  = tid >> 5;
    const int mw = wid >> 1, nw = wid & 1;
    const int blockRow = blockIdx.y * BM;
    const int colBase  = blockIdx.x * BN;

    const float* Ap = (MODE == 1) ? g_wsn : Afp;
    const __nv_bfloat16* Bth = (MODE == 0) ? g_Mth : g_Bth;
    const __nv_bfloat16* Btl = (MODE == 0) ? g_Mtl : g_Btl;

    float acc[2][8][4];
    #pragma unroll
    for (int t = 0; t < 2; t++)
        #pragma unroll
        for (int j = 0; j < 8; j++)
            #pragma unroll
            for (int c = 0; c < 4; c++) acc[t][j][c] = 0.0f;

    float4 ra[2][2];
    const int r0 = tid >> 2,         ch0 = tid & 3;
    const int r1 = (tid + 128) >> 2;
    auto ldgA = [&](int kt) {
        int g0 = blockRow + r0;
        bool a0 = g0 < nrows;
        const float4* s0 = (const float4*)(Ap + (size_t)(a0 ? g0 : 0) * HH + kt * BK + ch0 * 8);
        ra[0][0] = a0 ? s0[0] : make_float4(0.f, 0.f, 0.f, 0.f);
        ra[0][1] = a0 ? s0[1] : make_float4(0.f, 0.f, 0.f, 0.f);
        int g1 = blockRow + r1;
        bool a1 = g1 < nrows;
        const float4* s1 = (const float4*)(Ap + (size_t)(a1 ? g1 : 0) * HH + kt * BK + ch0 * 8);
        ra[1][0] = a1 ? s1[0] : make_float4(0.f, 0.f, 0.f, 0.f);
        ra[1][1] = a1 ? s1[1] : make_float4(0.f, 0.f, 0.f, 0.f);
    };
    auto stsA = [&](int s) {
        char* db = smem + s * STAGE_BYTES;
        #pragma unroll
        for (int l = 0; l < 2; l++) {
            int r = l ? r1 : r0;
            uint32_t dst = swz(r, ch0);
            uint32_t h0, h1, h2, h3, l0, l1, l2, l3;
            split2(ra[l][0].x, ra[l][0].y, h0, l0);
            split2(ra[l][0].z, ra[l][0].w, h1, l1);
            split2(ra[l][1].x, ra[l][1].y, h2, l2);
            split2(ra[l][1].z, ra[l][1].w, h3, l3);
            *(uint4*)(db + AH_OFF + dst) = make_uint4(h0, h1, h2, h3);
            *(uint4*)(db + AL_OFF + dst) = make_uint4(l0, l1, l2, l3);
        }
    };
    auto cpB = [&](int kt, int s) {
        uint32_t db = sbase + (uint32_t)s * STAGE_BYTES;
        #pragma unroll
        for (int l = 0; l < 4; l++) {
            int u = tid + l * 128;
            int r = u >> 2, ch = u & 3;
            size_t gb = (size_t)(colBase + r) * HH + kt * BK + ch * 8;
            uint32_t dst = swz(r, ch);
            cpa16(db + BH_OFF + dst, Bth + gb, true);
            cpa16(db + BL_OFF + dst, Btl + gb, true);
        }
        asm volatile("cp.async.commit_group;" ::: "memory");
    };

    ldgA(0); stsA(0);
    cpB(0, 0);
    ldgA(1);
    cpB(1, 1);

    const int NKT = HH / BK;   // 8
    for (int kt = 0; kt < NKT; kt++) {
        if (kt < NKT - 1) asm volatile("cp.async.wait_group 1;" ::: "memory");
        else              asm volatile("cp.async.wait_group 0;" ::: "memory");
        if (kt + 1 < NKT) stsA((kt + 1) & 1);
        __syncthreads();
        if (kt + 2 < NKT) ldgA(kt + 2);

        uint32_t sb = sbase + (uint32_t)(kt & 1) * STAGE_BYTES;
        #pragma unroll
        for (int k16 = 0; k16 < BK; k16 += 16) {
            uint32_t ah[2][4], al[2][4];
            #pragma unroll
            for (int t = 0; t < 2; t++) {
                int arow = mw * 32 + t * 16 + (lane & 15);
                int cb = (k16 >> 3) + (lane >> 4);
                uint32_t ao = swz(arow, cb);
                ldsm4(ah[t], sb + AH_OFF + ao);
                ldsm4(al[t], sb + AL_OFF + ao);
            }
            #pragma unroll
            for (int p = 0; p < 4; p++) {
                int brow = nw * 64 + p * 16 + (lane & 7) + ((lane >> 4) << 3);
                int cb = (k16 >> 3) + ((lane >> 3) & 1);
                uint32_t bo = swz(brow, cb);
                uint32_t bh[4], bl[4];
                ldsm4(bh, sb + BH_OFF + bo);
                ldsm4(bl, sb + BL_OFF + bo);
                #pragma unroll
                for (int t = 0; t < 2; t++)
                    #pragma unroll
                    for (int q = 0; q < 2; q++)
                        mma16816(acc[t][p * 2 + q], ah[t], &bh[2 * q]);
                #pragma unroll
                for (int t = 0; t < 2; t++)
                    #pragma unroll
                    for (int q = 0; q < 2; q++)
                        mma16816(acc[t][p * 2 + q], ah[t], &bl[2 * q]);
                #pragma unroll
                for (int t = 0; t < 2; t++)
                    #pragma unroll
                    for (int q = 0; q < 2; q++)
                        mma16816(acc[t][p * 2 + q], al[t], &bh[2 * q]);
            }
        }
        __syncthreads();
        if (kt + 2 < NKT) cpB(kt + 2, kt & 1);
    }

    const int lr = lane >> 2;
    const int lc = (lane & 3) * 2;

    if (MODE == 0) {
        float part[2][2] = {{0.f, 0.f}, {0.f, 0.f}};
        #pragma unroll
        for (int t = 0; t < 2; t++) {
            int row0 = blockRow + mw * 32 + t * 16 + lr;
            #pragma unroll
            for (int j = 0; j < 8; j++) {
                int col = colBase + nw * 64 + j * 8 + lc;
                if (row0 < nrows) {
                    float2 s = *(const float2*)&extra[(size_t)row0 * 256 + col];
                    part[t][0] += acc[t][j][0] * s.x + acc[t][j][1] * s.y;
                }
                if (row0 + 8 < nrows) {
                    float2 s = *(const float2*)&extra[(size_t)(row0 + 8) * 256 + col];
                    part[t][1] += acc[t][j][2] * s.x + acc[t][j][3] * s.y;
                }
            }
        }
        #pragma unroll
        for (int t = 0; t < 2; t++)
            #pragma unroll
            for (int h = 0; h < 2; h++) {
                part[t][h] += __shfl_xor_sync(0xffffffffu, part[t][h], 1);
                part[t][h] += __shfl_xor_sync(0xffffffffu, part[t][h], 2);
            }
        __syncthreads();
        float* red = (float*)smem;
        if ((lane & 3) == 0) {
            #pragma unroll
            for (int t = 0; t < 2; t++) {
                red[(mw * 32 + t * 16 + lr) * 2 + nw]     = part[t][0];
                red[(mw * 32 + t * 16 + lr + 8) * 2 + nw] = part[t][1];
            }
        }
        __syncthreads();
        if (tid < 64) {
            int row = blockRow + tid;
            if (row < nrows) {
                float s = red[tid * 2] + red[tid * 2 + 1];
                asm volatile("red.global.add.f32 [%0], %1;"
                             :: "l"(g_sim + row), "f"(s) : "memory");
            }
        }
    } else {
        #pragma unroll
        for (int t = 0; t < 2; t++)
            #pragma unroll
            for (int h = 0; h < 2; h++) {
                int row = blockRow + mw * 32 + t * 16 + lr + h * 8;
                if (row >= nrows) continue;
                #pragma unroll
                for (int j = 0; j < 8; j++) {
                    int col = colBase + nw * 64 + j * 8 + lc;
                    float2 b = *(const float2*)&extra[col];
                    float2 o;
                    o.x = acc[t][j][2 * h + 0] + b.x;
                    o.y = acc[t][j][2 * h + 1] + b.y;
                    *(float2*)&g_D[(size_t)row * 256 + col] = o;
                }
            }
    }
}

// ---------------- tf32 GEMM: g_P = ue @ C1 (fp16, epilogue deferred) -------------
__global__ __launch_bounds__(128, 4)
void k_tf(const float* __restrict__ Afp, int nrows) {
    extern __shared__ __align__(16) char smem[];
    uint32_t sbase = (uint32_t)__cvta_generic_to_shared(smem);
    const int tid  = threadIdx.x;
    const int lane = tid & 31;
    const int wid  = tid >> 5;
    const int mw = wid >> 1, nw = wid & 1;     // warp tile 32 x 64
    const int blockRow = blockIdx.y * BM;
    const int colBase  = blockIdx.x * BN;

    float acc[2][8][4];
    #pragma unroll
    for (int t = 0; t < 2; t++)
        #pragma unroll
        for (int j = 0; j < 8; j++)
            #pragma unroll
            for (int c = 0; c < 4; c++) acc[t][j][c] = 0.0f;

    auto load_stage = [&](int kt, int s) {
        uint32_t db = sbase + (uint32_t)s * TF_STAGE;
        #pragma unroll
        for (int l = 0; l < 4; l++) {
            int u = tid + l * 128;
            int r = u >> 3, ch = u & 7;
            int grow = blockRow + r;
            bool v = grow < nrows;
            size_t ga = (size_t)(v ? grow : 0) * HH + kt * BK + ch * 4;
            cpa16(db + TF_A_OFF + swz128(r, ch), Afp + ga, v);
        }
        #pragma unroll
        for (int l = 0; l < 8; l++) {
            int u = tid + l * 128;
            int r = u >> 3, ch = u & 7;
            size_t gb = (size_t)(colBase + r) * HH + kt * BK + ch * 4;
            cpa16(db + TF_B_OFF + swz128(r, ch), g_C1f + gb, true);
        }
        asm volatile("cp.async.commit_group;" ::: "memory");
    };

    load_stage(0, 0);
    load_stage(1, 1);

    const int NKT = HH / BK;   // 8
    for (int kt = 0; kt < NKT; kt++) {
        if (kt < NKT - 1) asm volatile("cp.async.wait_group 1;" ::: "memory");
        else              asm volatile("cp.async.wait_group 0;" ::: "memory");
        __syncthreads();

        uint32_t sb = sbase + (uint32_t)(kt & 1) * TF_STAGE;
        #pragma unroll
        for (int k8 = 0; k8 < 4; k8++) {
            uint32_t av[2][4];
            #pragma unroll
            for (int t = 0; t < 2; t++) {
                int arow = mw * 32 + t * 16 + (lane & 7) + ((lane >> 3) & 1) * 8;
                int ch = k8 * 2 + (lane >> 4);
                ldsm4(av[t], sb + TF_A_OFF + swz128(arow, ch));
                av[t][0] = rna(av[t][0]); av[t][1] = rna(av[t][1]);
                av[t][2] = rna(av[t][2]); av[t][3] = rna(av[t][3]);
            }
            #pragma unroll
            for (int p = 0; p < 4; p++) {
                int brow = nw * 64 + p * 16 + (lane & 7) + ((lane >> 4) << 3);
                int bch = k8 * 2 + ((lane >> 3) & 1);
                uint32_t bv[4];
                ldsm4(bv, sb + TF_B_OFF + swz128(brow, bch));
                #pragma unroll
                for (int t = 0; t < 2; t++)
                    #pragma unroll
                    for (int q = 0; q < 2; q++)
                        mma_tf(acc[t][p * 2 + q], av[t], &bv[2 * q]);
            }
        }
        __syncthreads();
        if (kt + 2 < NKT) load_stage(kt + 2, kt & 1);
    }

    const int lr = lane >> 2;
    const int lc = (lane & 3) * 2;
    #pragma unroll
    for (int t = 0; t < 2; t++)
        #pragma unroll
        for (int h = 0; h < 2; h++) {
            int row = blockRow + mw * 32 + t * 16 + lr + h * 8;
            if (row >= nrows) continue;
            #pragma unroll
            for (int j = 0; j < 8; j++) {
                int col = colBase + nw * 64 + j * 8 + lc;
                __half2 hp = __floats2half2_rn(acc[t][j][2 * h + 0], acc[t][j][2 * h + 1]);
                *(__half2*)&g_P[(size_t)row * 256 + col] = hp;
            }
        }
}

// ---------------- join epilogue: out = relu(P + D[ids]) --------------------------
__global__ void k_epi(float* __restrict__ outp, const int* __restrict__ ids, int n) {
    int gid = blockIdx.x * 256 + threadIdx.x;   // n*64 threads
    int row = gid >> 6;
    int c4  = (gid & 63) * 4;
    if (row >= n) return;
    int uid = ids[row];
    float2 p01 = __half22float2(*(const __half2*)&g_P[(size_t)row * 256 + c4]);
    float2 p23 = __half22float2(*(const __half2*)&g_P[(size_t)row * 256 + c4 + 2]);
    float4 d = *(const float4*)&g_D[(size_t)uid * 256 + c4];
    float4 o;
    o.x = fmaxf(p01.x + d.x, 0.0f);
    o.y = fmaxf(p01.y + d.y, 0.0f);
    o.z = fmaxf(p23.x + d.z, 0.0f);
    o.w = fmaxf(p23.y + d.w, 0.0f);
    *(float4*)&outp[(size_t)row * 256 + c4] = o;
}

// ---------------- launch ----------------------------------------------------------
extern "C" void kernel_launch(void* const* d_in, const int* in_sizes, int n_in,
                              void* d_out, int out_size) {
    const float* sess = (const float*)d_in[0];
    const float* ue   = (const float*)d_in[1];
    const int*   ids  = (const int*)d_in[2];   // JAX x64 disabled: int32
    const float* Wq   = (const float*)d_in[3];
    const float* Wk   = (const float*)d_in[4];
    const float* Wv   = (const float*)d_in[5];
    const float* W1   = (const float*)d_in[6];
    const float* b1   = (const float*)d_in[7];
    float*       out  = (float*)d_out;
    int N = in_sizes[0] / HH;   // 200000

    static cudaStream_t s1, s2;
    static cudaEvent_t eZero, eCsr, eM0, eTf;
    static bool init = false;
    if (!init) {
        cudaFuncSetAttribute(k_mma<0>, cudaFuncAttributeMaxDynamicSharedMemorySize, NSTAGE * STAGE_BYTES);
        cudaFuncSetAttribute(k_mma<1>, cudaFuncAttributeMaxDynamicSharedMemorySize, NSTAGE * STAGE_BYTES);
        cudaFuncSetAttribute(k_tf,     cudaFuncAttributeMaxDynamicSharedMemorySize, NSTAGE * TF_STAGE);
        cudaStreamCreateWithFlags(&s1, cudaStreamNonBlocking);
        cudaStreamCreateWithFlags(&s2, cudaStreamNonBlocking);
        cudaEventCreateWithFlags(&eZero, cudaEventDisableTiming);
        cudaEventCreateWithFlags(&eCsr,  cudaEventDisableTiming);
        cudaEventCreateWithFlags(&eM0,   cudaEventDisableTiming);
        cudaEventCreateWithFlags(&eTf,   cudaEventDisableTiming);
        init = true;
    }

    dim3 gBig(2, (N + BM - 1) / BM);
    dim3 gU(2, (UU + BM - 1) / BM);

    // main stream: zero
    k_zero<<<(NN + 255) / 256, 256>>>();

    // fork s1: CSR build (needs only ids + zeroed counters)
    cudaEventRecord(eZero, 0);
    cudaStreamWaitEvent(s1, eZero, 0);
    k_hist<<<(N + 255) / 256, 256, 0, s1>>>(ids, N);
    k_scan<<<1, 256, 0, s1>>>();
    k_fill<<<(N + 255) / 256, 256, 0, s1>>>(ids, N);
    cudaEventRecord(eCsr, s1);

    // main stream: weight prep (all three planes in one kernel)
    k_prepT<<<dim3(8, 8, 3), 256>>>(Wq, Wk, Wv, W1);

    // main stream: MODE 0 GEMM (6th submitted launch -> ncu -s 5 captures it)
    k_mma<0><<<gBig, 128, NSTAGE * STAGE_BYTES>>>(ue, sess, ids, nullptr, N);

    // fork s2: tf32 GEMM runs AFTER MODE0 (A/B: avoid GEMM-GEMM interference),
    // concurrent with the softmax path on the main stream.
    cudaEventRecord(eM0, 0);
    cudaStreamWaitEvent(s2, eM0, 0);
    k_tf<<<gBig, 128, NSTAGE * TF_STAGE, s2>>>(ue, N);
    cudaEventRecord(eTf, s2);

    // main stream: softmax path + U-level GEMM
    k_smax<<<(N + 255) / 256, 256>>>(ids, N);
    cudaStreamWaitEvent(0, eCsr, 0);
    k_gather<<<(UU + 3) / 4, 256>>>(ue);
    k_mma<1><<<gU, 128, NSTAGE * STAGE_BYTES>>>(nullptr, b1, nullptr, nullptr, UU);

    // join: epilogue needs P (s2) and g_D (main)
    cudaStreamWaitEvent(0, eTf, 0);
    k_epi<<<(N * 64 + 255) / 256, 256>>>(out, ids, N);
}